// round 2
// baseline (speedup 1.0000x reference)
#include <cuda_runtime.h>
#include <cstdint>

#define H 128
#define NN 100000
#define NE 400000
#define NI 800000
#define BN_EPS 1e-5f

// ---------------- scratch (static device allocations; allowed) ----------------
__device__ float g_P[NN * H];          // node_rep @ W1[:128]
__device__ float g_Q[NE * H];          // edge_rep @ W1[128:]
__device__ float g_cat[NE * 2 * H];    // segment sums per edge: [msg | node_rep]
__device__ float g_lvl[NN * H];        // segment sum per node
__device__ float g_h2[NN * H];
__device__ float g_t2[NN * H];
__device__ float g_h3[NE * H];
__device__ float g_t3[NE * H];
__device__ double g_sum[5][H];
__device__ double g_sq[5][H];
__device__ float g_scale[5][H];
__device__ float g_shift[5][H];

// ---------------- helpers ----------------
__device__ __forceinline__ void red4(float* p, float4 v) {
    asm volatile("red.global.add.v4.f32 [%0], {%1,%2,%3,%4};"
                 :: "l"(p), "f"(v.x), "f"(v.y), "f"(v.z), "f"(v.w) : "memory");
}

__device__ __forceinline__ float relu_aff(float x, float sc, float sh) {
    return fmaxf(fmaf(x, sc, sh), 0.f);
}

// ---------------- zero init ----------------
__global__ void __launch_bounds__(256) zero_k() {
    size_t gid = (size_t)blockIdx.x * blockDim.x + threadIdx.x;
    const size_t n_cat4 = (size_t)NE * 2 * H / 4;  // 25,600,000
    const size_t n_lvl4 = (size_t)NN * H / 4;      // 3,200,000
    float4 z = make_float4(0.f, 0.f, 0.f, 0.f);
    if (gid < n_cat4)               ((float4*)g_cat)[gid] = z;
    else if (gid < n_cat4 + n_lvl4) ((float4*)g_lvl)[gid - n_cat4] = z;
    if (gid < 5 * H) {
        (&g_sum[0][0])[gid] = 0.0;
        (&g_sq[0][0])[gid] = 0.0;
    }
}

// ---------------- fp32 SGEMM, K=N=128 fixed ----------------
// AMODE 0: A = A1
// AMODE 1: A = (1+*epsp)*A1 + A2   (A2 row stride lda2)
// AMODE 2: A = relu(A1*scale[inSet] + shift[inSet])  (column-wise affine)
// STATS  : accumulate per-column sum/sumsq of C into g_sum/g_sq[statSet]
template <int AMODE, bool STATS>
__global__ void __launch_bounds__(256)
gemm_k(const float* __restrict__ A1, const float* __restrict__ A2, int lda2,
       const float* __restrict__ epsp, const float* __restrict__ W,
       float* __restrict__ C, int M, int inSet, int statSet)
{
    __shared__ float As[16][64];
    __shared__ float Bs[16][128];
    const int tid = threadIdx.x;
    const int row0 = blockIdx.x * 64;
    const int ar = tid >> 2;            // A-load row 0..63
    const int ak = (tid & 3) << 2;      // A-load k 0,4,8,12
    const int ty = tid >> 4;            // compute row group 0..15
    const int tx = tid & 15;            // compute col group 0..15
    const int bk = tid >> 5;            // B-load k row 0..7
    const int bc = (tid & 31) << 2;     // B-load col 0..124

    float alpha = 0.f;
    if (AMODE == 1) alpha = 1.0f + __ldg(epsp);

    float acc[4][8];
#pragma unroll
    for (int i = 0; i < 4; i++)
#pragma unroll
        for (int j = 0; j < 8; j++) acc[i][j] = 0.f;

    const int arow = row0 + ar;
    const bool rvalid = arow < M;
    const float* a1p = A1 + (size_t)arow * H;
    const float* a2p = (AMODE == 1) ? (A2 + (size_t)arow * lda2) : nullptr;

    for (int kb = 0; kb < H; kb += 16) {
        float4 av = make_float4(0.f, 0.f, 0.f, 0.f);
        if (rvalid) {
            float4 v1 = *(const float4*)(a1p + kb + ak);
            if (AMODE == 0) {
                av = v1;
            } else if (AMODE == 1) {
                float4 v2 = *(const float4*)(a2p + kb + ak);
                av.x = fmaf(alpha, v1.x, v2.x);
                av.y = fmaf(alpha, v1.y, v2.y);
                av.z = fmaf(alpha, v1.z, v2.z);
                av.w = fmaf(alpha, v1.w, v2.w);
            } else {
                int c = kb + ak;
                av.x = relu_aff(v1.x, g_scale[inSet][c + 0], g_shift[inSet][c + 0]);
                av.y = relu_aff(v1.y, g_scale[inSet][c + 1], g_shift[inSet][c + 1]);
                av.z = relu_aff(v1.z, g_scale[inSet][c + 2], g_shift[inSet][c + 2]);
                av.w = relu_aff(v1.w, g_scale[inSet][c + 3], g_shift[inSet][c + 3]);
            }
        }
        As[ak + 0][ar] = av.x;
        As[ak + 1][ar] = av.y;
        As[ak + 2][ar] = av.z;
        As[ak + 3][ar] = av.w;
        *(float4*)&Bs[bk][bc]     = *(const float4*)(W + (size_t)(kb + bk) * H + bc);
        *(float4*)&Bs[bk + 8][bc] = *(const float4*)(W + (size_t)(kb + bk + 8) * H + bc);
        __syncthreads();
#pragma unroll
        for (int k = 0; k < 16; k++) {
            float4 a4 = *(const float4*)&As[k][ty << 2];
            float4 b0 = *(const float4*)&Bs[k][tx << 3];
            float4 b1 = *(const float4*)&Bs[k][(tx << 3) + 4];
            float a[4] = {a4.x, a4.y, a4.z, a4.w};
            float b[8] = {b0.x, b0.y, b0.z, b0.w, b1.x, b1.y, b1.z, b1.w};
#pragma unroll
            for (int i = 0; i < 4; i++)
#pragma unroll
                for (int j = 0; j < 8; j++)
                    acc[i][j] = fmaf(a[i], b[j], acc[i][j]);
        }
        __syncthreads();
    }

#pragma unroll
    for (int i = 0; i < 4; i++) {
        int r = row0 + (ty << 2) + i;
        if (r < M) {
            float* cp = C + (size_t)r * H + (tx << 3);
            *(float4*)cp       = make_float4(acc[i][0], acc[i][1], acc[i][2], acc[i][3]);
            *(float4*)(cp + 4) = make_float4(acc[i][4], acc[i][5], acc[i][6], acc[i][7]);
        }
    }

    if (STATS) {
        // OOB rows contributed acc==0 (As zero-filled) -> no effect on sums.
        float cs[8], cq[8];
#pragma unroll
        for (int j = 0; j < 8; j++) {
            float s = 0.f, q = 0.f;
#pragma unroll
            for (int i = 0; i < 4; i++) {
                s += acc[i][j];
                q = fmaf(acc[i][j], acc[i][j], q);
            }
            cs[j] = s; cq[j] = q;
        }
        float (*red)[128] = Bs;
        __syncthreads();
#pragma unroll
        for (int j = 0; j < 8; j++) red[ty][(tx << 3) + j] = cs[j];
        __syncthreads();
        if (tid < 128) {
            float s = 0.f;
#pragma unroll
            for (int t = 0; t < 16; t++) s += red[t][tid];
            atomicAdd(&g_sum[statSet][tid], (double)s);
        }
        __syncthreads();
#pragma unroll
        for (int j = 0; j < 8; j++) red[ty][(tx << 3) + j] = cq[j];
        __syncthreads();
        if (tid < 128) {
            float s = 0.f;
#pragma unroll
            for (int t = 0; t < 16; t++) s += red[t][tid];
            atomicAdd(&g_sq[statSet][tid], (double)s);
        }
    }
}

// ---------------- stats over msg_raw[i] = P[n_i] + Q[e_i] ----------------
__global__ void __launch_bounds__(256)
stats_msg_k(const int* __restrict__ node_idx, const int* __restrict__ edge_idx)
{
    const int lane = threadIdx.x & 31;
    const int w = threadIdx.x >> 5;
    const int c4 = lane << 2;
    float4 s = make_float4(0.f, 0.f, 0.f, 0.f);
    float4 q = make_float4(0.f, 0.f, 0.f, 0.f);
    for (int i = blockIdx.x * 8 + w; i < NI; i += gridDim.x * 8) {
        int n = node_idx[i], e = edge_idx[i];
        float4 p  = *(const float4*)(g_P + (size_t)n * H + c4);
        float4 qq = *(const float4*)(g_Q + (size_t)e * H + c4);
        float vx = p.x + qq.x, vy = p.y + qq.y, vz = p.z + qq.z, vw = p.w + qq.w;
        s.x += vx; s.y += vy; s.z += vz; s.w += vw;
        q.x = fmaf(vx, vx, q.x); q.y = fmaf(vy, vy, q.y);
        q.z = fmaf(vz, vz, q.z); q.w = fmaf(vw, vw, q.w);
    }
    __shared__ float red[8][128];
    red[w][c4 + 0] = s.x; red[w][c4 + 1] = s.y; red[w][c4 + 2] = s.z; red[w][c4 + 3] = s.w;
    __syncthreads();
    if (threadIdx.x < 128) {
        float t = 0.f;
#pragma unroll
        for (int r = 0; r < 8; r++) t += red[r][threadIdx.x];
        atomicAdd(&g_sum[0][threadIdx.x], (double)t);
    }
    __syncthreads();
    red[w][c4 + 0] = q.x; red[w][c4 + 1] = q.y; red[w][c4 + 2] = q.z; red[w][c4 + 3] = q.w;
    __syncthreads();
    if (threadIdx.x < 128) {
        float t = 0.f;
#pragma unroll
        for (int r = 0; r < 8; r++) t += red[r][threadIdx.x];
        atomicAdd(&g_sq[0][threadIdx.x], (double)t);
    }
}

// ---------------- finalize BN stats -> fused scale/shift ----------------
__global__ void finalize_k(int set, const float* __restrict__ g,
                           const float* __restrict__ b, float invN)
{
    int j = threadIdx.x;  // 128 threads
    double mean = g_sum[set][j] * (double)invN;
    double var = g_sq[set][j] * (double)invN - mean * mean;
    float sc = g[j] * rsqrtf((float)var + BN_EPS);
    g_scale[set][j] = sc;
    g_shift[set][j] = fmaf(-(float)mean, sc, b[j]);
}

// ---------------- build cat: segment sum of [msg | node_rep] by edge ----------------
__global__ void __launch_bounds__(256)
cat_k(const float* __restrict__ node_rep,
      const int* __restrict__ node_idx, const int* __restrict__ edge_idx)
{
    const int lane = threadIdx.x & 31;
    const int w = threadIdx.x >> 5;
    const int c4 = lane << 2;
    int i = blockIdx.x * 8 + w;
    if (i >= NI) return;
    int n = node_idx[i], e = edge_idx[i];
    float4 p = *(const float4*)(g_P + (size_t)n * H + c4);
    float4 q = *(const float4*)(g_Q + (size_t)e * H + c4);
    float4 sc = *(const float4*)&g_scale[0][c4];
    float4 sh = *(const float4*)&g_shift[0][c4];
    float4 m;
    m.x = relu_aff(p.x + q.x, sc.x, sh.x);
    m.y = relu_aff(p.y + q.y, sc.y, sh.y);
    m.z = relu_aff(p.z + q.z, sc.z, sh.z);
    m.w = relu_aff(p.w + q.w, sc.w, sh.w);
    red4(g_cat + (size_t)e * (2 * H) + c4, m);
    float4 nr = *(const float4*)(node_rep + (size_t)n * H + c4);
    red4(g_cat + (size_t)e * (2 * H) + H + c4, nr);
}

// ---------------- build lvl: segment sum of (cat[e,:H] - msg) by node ----------------
__global__ void __launch_bounds__(256)
lvl_k(const int* __restrict__ node_idx, const int* __restrict__ edge_idx)
{
    const int lane = threadIdx.x & 31;
    const int w = threadIdx.x >> 5;
    const int c4 = lane << 2;
    int i = blockIdx.x * 8 + w;
    if (i >= NI) return;
    int n = node_idx[i], e = edge_idx[i];
    float4 p = *(const float4*)(g_P + (size_t)n * H + c4);
    float4 q = *(const float4*)(g_Q + (size_t)e * H + c4);
    float4 sc = *(const float4*)&g_scale[0][c4];
    float4 sh = *(const float4*)&g_shift[0][c4];
    float4 cv = *(const float4*)(g_cat + (size_t)e * (2 * H) + c4);
    float4 d;
    d.x = cv.x - relu_aff(p.x + q.x, sc.x, sh.x);
    d.y = cv.y - relu_aff(p.y + q.y, sc.y, sh.y);
    d.z = cv.z - relu_aff(p.z + q.z, sc.z, sh.z);
    d.w = cv.w - relu_aff(p.w + q.w, sc.w, sh.w);
    red4(g_lvl + (size_t)n * H + c4, d);
}

// ---------------- final elementwise bn_relu to output ----------------
__global__ void __launch_bounds__(256)
bnout_k(const float* __restrict__ in, int set, float* __restrict__ out, int n4)
{
    int t = blockIdx.x * blockDim.x + threadIdx.x;
    if (t >= n4) return;
    int c4 = (t & 31) << 2;
    float4 v = ((const float4*)in)[t];
    float4 sc = *(const float4*)&g_scale[set][c4];
    float4 sh = *(const float4*)&g_shift[set][c4];
    float4 o;
    o.x = relu_aff(v.x, sc.x, sh.x);
    o.y = relu_aff(v.y, sc.y, sh.y);
    o.z = relu_aff(v.z, sc.z, sh.z);
    o.w = relu_aff(v.w, sc.w, sh.w);
    ((float4*)out)[t] = o;
}

// ---------------- launch ----------------
extern "C" void kernel_launch(void* const* d_in, const int* in_sizes, int n_in,
                              void* d_out, int out_size)
{
    const float* node_rep = (const float*)d_in[0];
    const float* edge_rep = (const float*)d_in[1];
    const int*   node_idx = (const int*)d_in[2];
    const int*   edge_idx = (const int*)d_in[3];
    const float* W1  = (const float*)d_in[4];
    const float* g1  = (const float*)d_in[5];
    const float* b1  = (const float*)d_in[6];
    const float* W2a = (const float*)d_in[7];
    const float* g2a = (const float*)d_in[8];
    const float* b2a = (const float*)d_in[9];
    const float* W2b = (const float*)d_in[10];
    const float* g2b = (const float*)d_in[11];
    const float* b2b = (const float*)d_in[12];
    const float* W3a = (const float*)d_in[13];
    const float* g3a = (const float*)d_in[14];
    const float* b3a = (const float*)d_in[15];
    const float* W3b = (const float*)d_in[16];
    const float* g3b = (const float*)d_in[17];
    const float* b3b = (const float*)d_in[18];
    const float* eps1 = (const float*)d_in[19];
    const float* eps2 = (const float*)d_in[20];

    float *P, *Q, *cat, *lvl, *h2, *t2, *h3, *t3;
    cudaGetSymbolAddress((void**)&P,   g_P);
    cudaGetSymbolAddress((void**)&Q,   g_Q);
    cudaGetSymbolAddress((void**)&cat, g_cat);
    cudaGetSymbolAddress((void**)&lvl, g_lvl);
    cudaGetSymbolAddress((void**)&h2,  g_h2);
    cudaGetSymbolAddress((void**)&t2,  g_t2);
    cudaGetSymbolAddress((void**)&h3,  g_h3);
    cudaGetSymbolAddress((void**)&t3,  g_t3);

    float* node_out = (float*)d_out;
    float* edge_out = (float*)d_out + (size_t)NN * H;

    // zero cat/lvl/stat accumulators
    zero_k<<<112500, 256>>>();

    // P = node_rep @ W1[:128], Q = edge_rep @ W1[128:]
    gemm_k<0, false><<<(NN + 63) / 64, 256>>>(node_rep, nullptr, 0, nullptr, W1,      P, NN, 0, 0);
    gemm_k<0, false><<<(NE + 63) / 64, 256>>>(edge_rep, nullptr, 0, nullptr, W1 + H*H, Q, NE, 0, 0);

    // BN1 stats over msg_raw gathers, finalize
    stats_msg_k<<<1184, 256>>>(node_idx, edge_idx);
    finalize_k<<<1, 128>>>(0, g1, b1, 1.0f / NI);

    // segment sums
    cat_k<<<NI / 8, 256>>>(node_rep, node_idx, edge_idx);
    lvl_k<<<NI / 8, 256>>>(node_idx, edge_idx);

    // node path: x = (1+eps1)*node_rep + lvl ; bn_relu(x@W2a)@W2b ; bn_relu -> out
    gemm_k<1, true><<<(NN + 63) / 64, 256>>>(node_rep, lvl, H, eps1, W2a, h2, NN, 0, 1);
    finalize_k<<<1, 128>>>(1, g2a, b2a, 1.0f / NN);
    gemm_k<2, true><<<(NN + 63) / 64, 256>>>(h2, nullptr, 0, nullptr, W2b, t2, NN, 1, 2);
    finalize_k<<<1, 128>>>(2, g2b, b2b, 1.0f / NN);
    bnout_k<<<(NN * H / 4 + 255) / 256, 256>>>(t2, 2, node_out, NN * H / 4);

    // edge path: y = (1+eps2)*edge_rep + cat[:,H:] ; bn_relu(y@W3a)@W3b ; bn_relu -> out
    gemm_k<1, true><<<(NE + 63) / 64, 256>>>(edge_rep, cat + H, 2 * H, eps2, W3a, h3, NE, 0, 3);
    finalize_k<<<1, 128>>>(3, g3a, b3a, 1.0f / NE);
    gemm_k<2, true><<<(NE + 63) / 64, 256>>>(h3, nullptr, 0, nullptr, W3b, t3, NE, 3, 4);
    finalize_k<<<1, 128>>>(4, g3b, b3b, 1.0f / NE);
    bnout_k<<<(NE * H / 4 + 255) / 256, 256>>>(t3, 4, edge_out, NE * H / 4);
}

// round 5
// speedup vs baseline: 1.1697x; 1.1697x over previous
#include <cuda_runtime.h>
#include <cuda_bf16.h>
#include <cstdint>

#define H 128
#define NN 100000
#define NE 400000
#define NI 800000
#define BN_EPS 1e-5f

// ---------------- scratch ----------------
__device__ float g_P[NN * H];
__device__ float g_Q[NE * H];
__device__ float g_cat[NE * 2 * H];
__device__ float g_lvl[NN * H];
__device__ float g_h2[NN * H];
__device__ float g_t2[NN * H];
__device__ float g_h3[NE * H];
__device__ float g_t3[NE * H];
__device__ double g_sum[5][H];
__device__ double g_sq[5][H];
__device__ float g_scale[5][H];
__device__ float g_shift[5][H];
// Preconverted weights: [n][k] bf16, 16B-granule XOR swizzle pre-applied.
__device__ __nv_bfloat16 g_Whi[6][H * H];
__device__ __nv_bfloat16 g_Wlo[6][H * H];

// ---------------- helpers ----------------
__device__ __forceinline__ uint32_t smem_u32(const void* p) {
    uint32_t a;
    asm("{ .reg .u64 t; cvta.to.shared.u64 t, %1; cvt.u32.u64 %0, t; }" : "=r"(a) : "l"(p));
    return a;
}
__device__ __forceinline__ void ldsm_x4(uint32_t r[4], uint32_t a) {
    asm volatile("ldmatrix.sync.aligned.m8n8.x4.shared.b16 {%0,%1,%2,%3}, [%4];"
                 : "=r"(r[0]), "=r"(r[1]), "=r"(r[2]), "=r"(r[3]) : "r"(a));
}
__device__ __forceinline__ void ldsm_x2(uint32_t r[2], uint32_t a) {
    asm volatile("ldmatrix.sync.aligned.m8n8.x2.shared.b16 {%0,%1}, [%2];"
                 : "=r"(r[0]), "=r"(r[1]) : "r"(a));
}
__device__ __forceinline__ void mma16816(float c[4], const uint32_t a[4], const uint32_t b[2]) {
    asm volatile("mma.sync.aligned.m16n8k16.row.col.f32.bf16.bf16.f32 "
                 "{%0,%1,%2,%3}, {%4,%5,%6,%7}, {%8,%9}, {%0,%1,%2,%3};"
                 : "+f"(c[0]), "+f"(c[1]), "+f"(c[2]), "+f"(c[3])
                 : "r"(a[0]), "r"(a[1]), "r"(a[2]), "r"(a[3]), "r"(b[0]), "r"(b[1]));
}
__device__ __forceinline__ void red4(float* p, float4 v) {
    asm volatile("red.global.add.v4.f32 [%0], {%1,%2,%3,%4};"
                 :: "l"(p), "f"(v.x), "f"(v.y), "f"(v.z), "f"(v.w) : "memory");
}
__device__ __forceinline__ float relu_aff(float x, float sc, float sh) {
    return fmaxf(fmaf(x, sc, sh), 0.f);
}

// ---------------- zero init ----------------
__global__ void __launch_bounds__(256) zero_k() {
    size_t gid = (size_t)blockIdx.x * blockDim.x + threadIdx.x;
    const size_t n_cat4 = (size_t)NE * 2 * H / 4;
    const size_t n_lvl4 = (size_t)NN * H / 4;
    float4 z = make_float4(0.f, 0.f, 0.f, 0.f);
    if (gid < n_cat4)               ((float4*)g_cat)[gid] = z;
    else if (gid < n_cat4 + n_lvl4) ((float4*)g_lvl)[gid - n_cat4] = z;
    if (gid < 5 * H) {
        (&g_sum[0][0])[gid] = 0.0;
        (&g_sq[0][0])[gid] = 0.0;
    }
}

// ---------------- preconvert weights: W[k][n] -> hi/lo bf16 [n][k], pre-swizzled ----------------
__global__ void __launch_bounds__(256)
wconv_k(const float* __restrict__ W1, const float* __restrict__ W2a,
        const float* __restrict__ W2b, const float* __restrict__ W3a,
        const float* __restrict__ W3b)
{
    int m = blockIdx.x;
    const float* src;
    switch (m) {
        case 0: src = W1; break;
        case 1: src = W1 + H * H; break;
        case 2: src = W2a; break;
        case 3: src = W2b; break;
        case 4: src = W3a; break;
        default: src = W3b; break;
    }
    for (int idx = threadIdx.x; idx < H * H; idx += 256) {
        int n = idx >> 7, k = idx & 127;
        float v = src[k * H + n];
        uint32_t uv = __float_as_uint(v);
        uint32_t hb = uv & 0xFFFF0000u;
        float res = v - __uint_as_float(hb);
        // [n][k] layout, 16B granules (8 bf16) swizzled: gran' = (k>>3) ^ (n&7)
        uint32_t off = (uint32_t)n * 128u + ((((uint32_t)k >> 3) ^ ((uint32_t)n & 7)) << 3)
                     + ((uint32_t)k & 7);
        g_Whi[m][off] = __ushort_as_bfloat16((unsigned short)(hb >> 16));
        g_Wlo[m][off] = __float2bfloat16(res);
    }
}

// ---------------- mma.sync GEMM: C[M,128] = A[M,128] @ W, 3-way bf16 split ----------------
// AMODE 0: A = A1
// AMODE 1: A = (1+*epsp)*A1 + A2 (row stride lda2)
// AMODE 2: A = relu(A1*scale[inSet] + shift[inSet])
// STATS : fused per-column sum/sumsq of C into g_sum/g_sq[statSet]
#define SMA_HI 0
#define SMA_LO 32768
#define SMW_HI 65536
#define SMW_LO 98304
#define SM_RED 131072
#define SMEM_BYTES (131072 + 1024)

template <int AMODE, bool STATS>
__global__ void __launch_bounds__(256)
gemm_mma(const float* __restrict__ A1, const float* __restrict__ A2, int lda2,
         const float* __restrict__ epsp,
         const __nv_bfloat16* __restrict__ Whi, const __nv_bfloat16* __restrict__ Wlo,
         float* __restrict__ C, int M, int inSet, int statSet)
{
    extern __shared__ char smem[];
    uint32_t sb = smem_u32(smem);
    const int tid = threadIdx.x;
    const int lane = tid & 31;
    const int wid = tid >> 5;

    // copy pre-swizzled W images (32KB each)
    {
        const uint4* shi = (const uint4*)Whi;
        const uint4* slo = (const uint4*)Wlo;
        uint4* dhi = (uint4*)(smem + SMW_HI);
        uint4* dlo = (uint4*)(smem + SMW_LO);
#pragma unroll
        for (int i = 0; i < 8; i++) {
            dhi[tid + i * 256] = shi[tid + i * 256];
            dlo[tid + i * 256] = slo[tid + i * 256];
        }
    }

    // load A rows, apply AMODE transform, split hi/lo, store swizzled
    {
        const int r = tid >> 1;
        const int cb = (tid & 1) << 6;
        const int arow = blockIdx.x * 128 + r;
        const bool valid = arow < M;
        float alpha = 0.f;
        if (AMODE == 1) alpha = 1.0f + __ldg(epsp);
        const float* a1p = A1 + (size_t)arow * H + cb;
        const float* a2p = (AMODE == 1) ? (A2 + (size_t)arow * lda2 + cb) : nullptr;
#pragma unroll
        for (int g = 0; g < 8; g++) {
            float f[8];
            if (valid) {
                float4 u0 = *(const float4*)(a1p + g * 8);
                float4 u1 = *(const float4*)(a1p + g * 8 + 4);
                f[0] = u0.x; f[1] = u0.y; f[2] = u0.z; f[3] = u0.w;
                f[4] = u1.x; f[5] = u1.y; f[6] = u1.z; f[7] = u1.w;
                if (AMODE == 1) {
                    float4 w0 = *(const float4*)(a2p + g * 8);
                    float4 w1 = *(const float4*)(a2p + g * 8 + 4);
                    f[0] = fmaf(alpha, f[0], w0.x); f[1] = fmaf(alpha, f[1], w0.y);
                    f[2] = fmaf(alpha, f[2], w0.z); f[3] = fmaf(alpha, f[3], w0.w);
                    f[4] = fmaf(alpha, f[4], w1.x); f[5] = fmaf(alpha, f[5], w1.y);
                    f[6] = fmaf(alpha, f[6], w1.z); f[7] = fmaf(alpha, f[7], w1.w);
                } else if (AMODE == 2) {
                    int c0 = cb + g * 8;
#pragma unroll
                    for (int j = 0; j < 8; j++)
                        f[j] = relu_aff(f[j], g_scale[inSet][c0 + j], g_shift[inSet][c0 + j]);
                }
            } else {
#pragma unroll
                for (int j = 0; j < 8; j++) f[j] = 0.f;
            }
            uint32_t hv[4], lv[4];
#pragma unroll
            for (int j = 0; j < 4; j++) {
                float a = f[2 * j], b = f[2 * j + 1];
                uint32_t ua = __float_as_uint(a), ub = __float_as_uint(b);
                hv[j] = __byte_perm(ua, ub, 0x7632);
                float ra = a - __uint_as_float(ua & 0xFFFF0000u);
                float rb = b - __uint_as_float(ub & 0xFFFF0000u);
                __nv_bfloat162 lo2 = __floats2bfloat162_rn(ra, rb);
                lv[j] = *(uint32_t*)&lo2;
            }
            uint32_t gran = (uint32_t)(((cb >> 3) + g) ^ (r & 7));
            uint32_t off = (uint32_t)r * 256u + gran * 16u;
            *(uint4*)(smem + SMA_HI + off) = make_uint4(hv[0], hv[1], hv[2], hv[3]);
            *(uint4*)(smem + SMA_LO + off) = make_uint4(lv[0], lv[1], lv[2], lv[3]);
        }
    }
    if (STATS) ((float*)(smem + SM_RED))[tid] = 0.f;  // 256 floats: sum[128] | sq[128]
    __syncthreads();

    const int wm = wid & 3;       // row block (32 rows)
    const int wn = wid >> 2;      // col block (64 cols)
    const int rb = wm * 32;
    const int cbc = wn * 64;

    float acc[2][8][4];
#pragma unroll
    for (int mt = 0; mt < 2; mt++)
#pragma unroll
        for (int j = 0; j < 8; j++)
#pragma unroll
            for (int q = 0; q < 4; q++) acc[mt][j][q] = 0.f;

#pragma unroll
    for (int ks = 0; ks < 8; ks++) {
        const uint32_t kg = (uint32_t)ks * 2u;
        uint32_t ahi[2][4], alo[2][4];
#pragma unroll
        for (int mt = 0; mt < 2; mt++) {
            uint32_t rowA = (uint32_t)(rb + mt * 16 + (lane & 15));
            uint32_t gran = (kg + (uint32_t)(lane >> 4)) ^ (rowA & 7u);
            uint32_t a = sb + SMA_HI + rowA * 256u + gran * 16u;
            ldsm_x4(ahi[mt], a);
            ldsm_x4(alo[mt], a + 32768u);
        }
#pragma unroll
        for (int j = 0; j < 8; j++) {
            uint32_t rowB = (uint32_t)(cbc + j * 8 + (lane & 7));
            uint32_t gran = (kg + (uint32_t)((lane >> 3) & 1)) ^ (rowB & 7u);
            uint32_t b = sb + SMW_HI + rowB * 256u + gran * 16u;
            uint32_t bh[2], bl[2];
            ldsm_x2(bh, b);
            ldsm_x2(bl, b + 32768u);
#pragma unroll
            for (int mt = 0; mt < 2; mt++) {
                mma16816(acc[mt][j], ahi[mt], bh);
                mma16816(acc[mt][j], ahi[mt], bl);
                mma16816(acc[mt][j], alo[mt], bh);
            }
        }
    }

    // epilogue: direct global stores (float2 per fragment row)
    const int gq = lane >> 2, rq = lane & 3;
#pragma unroll
    for (int mt = 0; mt < 2; mt++) {
        int r0 = blockIdx.x * 128 + rb + mt * 16 + gq;
#pragma unroll
        for (int j = 0; j < 8; j++) {
            int col = cbc + j * 8 + rq * 2;
            if (r0 < M)
                *(float2*)(C + (size_t)r0 * H + col) = make_float2(acc[mt][j][0], acc[mt][j][1]);
            if (r0 + 8 < M)
                *(float2*)(C + (size_t)(r0 + 8) * H + col) = make_float2(acc[mt][j][2], acc[mt][j][3]);
        }
    }

    if (STATS) {
        float* s_sum = (float*)(smem + SM_RED);
        float* s_sq  = s_sum + 128;
#pragma unroll
        for (int j = 0; j < 8; j++) {
            float se = 0.f, so = 0.f, qe = 0.f, qo = 0.f;
#pragma unroll
            for (int mt = 0; mt < 2; mt++) {
                float c0 = acc[mt][j][0], c1 = acc[mt][j][1];
                float c2 = acc[mt][j][2], c3 = acc[mt][j][3];
                se += c0 + c2; so += c1 + c3;
                qe = fmaf(c0, c0, qe); qe = fmaf(c2, c2, qe);
                qo = fmaf(c1, c1, qo); qo = fmaf(c3, c3, qo);
            }
#pragma unroll
            for (int o = 16; o >= 4; o >>= 1) {
                se += __shfl_down_sync(0xFFFFFFFFu, se, o);
                so += __shfl_down_sync(0xFFFFFFFFu, so, o);
                qe += __shfl_down_sync(0xFFFFFFFFu, qe, o);
                qo += __shfl_down_sync(0xFFFFFFFFu, qo, o);
            }
            if (lane < 4) {
                int col = cbc + j * 8 + lane * 2;
                atomicAdd(&s_sum[col],     se);
                atomicAdd(&s_sum[col + 1], so);
                atomicAdd(&s_sq[col],      qe);
                atomicAdd(&s_sq[col + 1],  qo);
            }
        }
        __syncthreads();
        if (tid < 128)      atomicAdd(&g_sum[statSet][tid],       (double)s_sum[tid]);
        else                atomicAdd(&g_sq[statSet][tid - 128],  (double)s_sq[tid - 128]);
    }
}

// ---------------- stats over msg_raw[i] = P[n_i] + Q[e_i] ----------------
__global__ void __launch_bounds__(256)
stats_msg_k(const int* __restrict__ node_idx, const int* __restrict__ edge_idx)
{
    const int lane = threadIdx.x & 31;
    const int w = threadIdx.x >> 5;
    const int c4 = lane << 2;
    float4 s = make_float4(0.f, 0.f, 0.f, 0.f);
    float4 q = make_float4(0.f, 0.f, 0.f, 0.f);
    for (int i = blockIdx.x * 8 + w; i < NI; i += gridDim.x * 8) {
        int n = node_idx[i], e = edge_idx[i];
        float4 p  = *(const float4*)(g_P + (size_t)n * H + c4);
        float4 qq = *(const float4*)(g_Q + (size_t)e * H + c4);
        float vx = p.x + qq.x, vy = p.y + qq.y, vz = p.z + qq.z, vw = p.w + qq.w;
        s.x += vx; s.y += vy; s.z += vz; s.w += vw;
        q.x = fmaf(vx, vx, q.x); q.y = fmaf(vy, vy, q.y);
        q.z = fmaf(vz, vz, q.z); q.w = fmaf(vw, vw, q.w);
    }
    __shared__ float red[8][128];
    red[w][c4 + 0] = s.x; red[w][c4 + 1] = s.y; red[w][c4 + 2] = s.z; red[w][c4 + 3] = s.w;
    __syncthreads();
    if (threadIdx.x < 128) {
        float t = 0.f;
#pragma unroll
        for (int r = 0; r < 8; r++) t += red[r][threadIdx.x];
        atomicAdd(&g_sum[0][threadIdx.x], (double)t);
    }
    __syncthreads();
    red[w][c4 + 0] = q.x; red[w][c4 + 1] = q.y; red[w][c4 + 2] = q.z; red[w][c4 + 3] = q.w;
    __syncthreads();
    if (threadIdx.x < 128) {
        float t = 0.f;
#pragma unroll
        for (int r = 0; r < 8; r++) t += red[r][threadIdx.x];
        atomicAdd(&g_sq[0][threadIdx.x], (double)t);
    }
}

// ---------------- finalize BN stats ----------------
__global__ void finalize_k(int set, const float* __restrict__ g,
                           const float* __restrict__ b, float invN)
{
    int j = threadIdx.x;
    double mean = g_sum[set][j] * (double)invN;
    double var = g_sq[set][j] * (double)invN - mean * mean;
    float sc = g[j] * rsqrtf((float)var + BN_EPS);
    g_scale[set][j] = sc;
    g_shift[set][j] = fmaf(-(float)mean, sc, b[j]);
}

// ---------------- segment scatter kernels ----------------
__global__ void __launch_bounds__(256)
cat_k(const float* __restrict__ node_rep,
      const int* __restrict__ node_idx, const int* __restrict__ edge_idx)
{
    const int lane = threadIdx.x & 31;
    const int w = threadIdx.x >> 5;
    const int c4 = lane << 2;
    int i = blockIdx.x * 8 + w;
    if (i >= NI) return;
    int n = node_idx[i], e = edge_idx[i];
    float4 p = *(const float4*)(g_P + (size_t)n * H + c4);
    float4 q = *(const float4*)(g_Q + (size_t)e * H + c4);
    float4 sc = *(const float4*)&g_scale[0][c4];
    float4 sh = *(const float4*)&g_shift[0][c4];
    float4 m;
    m.x = relu_aff(p.x + q.x, sc.x, sh.x);
    m.y = relu_aff(p.y + q.y, sc.y, sh.y);
    m.z = relu_aff(p.z + q.z, sc.z, sh.z);
    m.w = relu_aff(p.w + q.w, sc.w, sh.w);
    red4(g_cat + (size_t)e * (2 * H) + c4, m);
    float4 nr = *(const float4*)(node_rep + (size_t)n * H + c4);
    red4(g_cat + (size_t)e * (2 * H) + H + c4, nr);
}

__global__ void __launch_bounds__(256)
lvl_k(const int* __restrict__ node_idx, const int* __restrict__ edge_idx)
{
    const int lane = threadIdx.x & 31;
    const int w = threadIdx.x >> 5;
    const int c4 = lane << 2;
    int i = blockIdx.x * 8 + w;
    if (i >= NI) return;
    int n = node_idx[i], e = edge_idx[i];
    float4 p = *(const float4*)(g_P + (size_t)n * H + c4);
    float4 q = *(const float4*)(g_Q + (size_t)e * H + c4);
    float4 sc = *(const float4*)&g_scale[0][c4];
    float4 sh = *(const float4*)&g_shift[0][c4];
    float4 cv = *(const float4*)(g_cat + (size_t)e * (2 * H) + c4);
    float4 d;
    d.x = cv.x - relu_aff(p.x + q.x, sc.x, sh.x);
    d.y = cv.y - relu_aff(p.y + q.y, sc.y, sh.y);
    d.z = cv.z - relu_aff(p.z + q.z, sc.z, sh.z);
    d.w = cv.w - relu_aff(p.w + q.w, sc.w, sh.w);
    red4(g_lvl + (size_t)n * H + c4, d);
}

// ---------------- final elementwise bn_relu ----------------
__global__ void __launch_bounds__(256)
bnout_k(const float* __restrict__ in, int set, float* __restrict__ out, int n4)
{
    int t = blockIdx.x * blockDim.x + threadIdx.x;
    if (t >= n4) return;
    int c4 = (t & 31) << 2;
    float4 v = ((const float4*)in)[t];
    float4 sc = *(const float4*)&g_scale[set][c4];
    float4 sh = *(const float4*)&g_shift[set][c4];
    float4 o;
    o.x = relu_aff(v.x, sc.x, sh.x);
    o.y = relu_aff(v.y, sc.y, sh.y);
    o.z = relu_aff(v.z, sc.z, sh.z);
    o.w = relu_aff(v.w, sc.w, sh.w);
    ((float4*)out)[t] = o;
}

// ---------------- launch ----------------
extern "C" void kernel_launch(void* const* d_in, const int* in_sizes, int n_in,
                              void* d_out, int out_size)
{
    const float* node_rep = (const float*)d_in[0];
    const float* edge_rep = (const float*)d_in[1];
    const int*   node_idx = (const int*)d_in[2];
    const int*   edge_idx = (const int*)d_in[3];
    const float* W1  = (const float*)d_in[4];
    const float* g1  = (const float*)d_in[5];
    const float* b1  = (const float*)d_in[6];
    const float* W2a = (const float*)d_in[7];
    const float* g2a = (const float*)d_in[8];
    const float* b2a = (const float*)d_in[9];
    const float* W2b = (const float*)d_in[10];
    const float* g2b = (const float*)d_in[11];
    const float* b2b = (const float*)d_in[12];
    const float* W3a = (const float*)d_in[13];
    const float* g3a = (const float*)d_in[14];
    const float* b3a = (const float*)d_in[15];
    const float* W3b = (const float*)d_in[16];
    const float* g3b = (const float*)d_in[17];
    const float* b3b = (const float*)d_in[18];
    const float* eps1 = (const float*)d_in[19];
    const float* eps2 = (const float*)d_in[20];

    float *P, *Q, *cat, *lvl, *h2, *t2, *h3, *t3;
    __nv_bfloat16 *Whi, *Wlo;
    cudaGetSymbolAddress((void**)&P,   g_P);
    cudaGetSymbolAddress((void**)&Q,   g_Q);
    cudaGetSymbolAddress((void**)&cat, g_cat);
    cudaGetSymbolAddress((void**)&lvl, g_lvl);
    cudaGetSymbolAddress((void**)&h2,  g_h2);
    cudaGetSymbolAddress((void**)&t2,  g_t2);
    cudaGetSymbolAddress((void**)&h3,  g_h3);
    cudaGetSymbolAddress((void**)&t3,  g_t3);
    cudaGetSymbolAddress((void**)&Whi, g_Whi);
    cudaGetSymbolAddress((void**)&Wlo, g_Wlo);

    cudaFuncSetAttribute(gemm_mma<0, false>, cudaFuncAttributeMaxDynamicSharedMemorySize, SMEM_BYTES);
    cudaFuncSetAttribute(gemm_mma<1, true>,  cudaFuncAttributeMaxDynamicSharedMemorySize, SMEM_BYTES);
    cudaFuncSetAttribute(gemm_mma<2, true>,  cudaFuncAttributeMaxDynamicSharedMemorySize, SMEM_BYTES);

    float* node_out = (float*)d_out;
    float* edge_out = (float*)d_out + (size_t)NN * H;

    const int GN = (NN + 127) / 128;   // 782
    const int GE = (NE + 127) / 128;   // 3125

    zero_k<<<112500, 256>>>();
    wconv_k<<<6, 256>>>(W1, W2a, W2b, W3a, W3b);

    // P = node_rep @ W1[:128], Q = edge_rep @ W1[128:]
    gemm_mma<0, false><<<GN, 256, SMEM_BYTES>>>(node_rep, nullptr, 0, nullptr,
                                                Whi + 0 * H * H, Wlo + 0 * H * H, P, NN, 0, 0);
    gemm_mma<0, false><<<GE, 256, SMEM_BYTES>>>(edge_rep, nullptr, 0, nullptr,
                                                Whi + 1 * H * H, Wlo + 1 * H * H, Q, NE, 0, 0);

    stats_msg_k<<<1184, 256>>>(node_idx, edge_idx);
    finalize_k<<<1, 128>>>(0, g1, b1, 1.0f / NI);

    cat_k<<<NI / 8, 256>>>(node_rep, node_idx, edge_idx);
    lvl_k<<<NI / 8, 256>>>(node_idx, edge_idx);

    // node path
    gemm_mma<1, true><<<GN, 256, SMEM_BYTES>>>(node_rep, lvl, H, eps1,
                                               Whi + 2 * H * H, Wlo + 2 * H * H, h2, NN, 0, 1);
    finalize_k<<<1, 128>>>(1, g2a, b2a, 1.0f / NN);
    gemm_mma<2, true><<<GN, 256, SMEM_BYTES>>>(h2, nullptr, 0, nullptr,
                                               Whi + 3 * H * H, Wlo + 3 * H * H, t2, NN, 1, 2);
    finalize_k<<<1, 128>>>(2, g2b, b2b, 1.0f / NN);
    bnout_k<<<(NN * H / 4 + 255) / 256, 256>>>(t2, 2, node_out, NN * H / 4);

    // edge path
    gemm_mma<1, true><<<GE, 256, SMEM_BYTES>>>(edge_rep, cat + H, 2 * H, eps2,
                                               Whi + 4 * H * H, Wlo + 4 * H * H, h3, NE, 0, 3);
    finalize_k<<<1, 128>>>(3, g3a, b3a, 1.0f / NE);
    gemm_mma<2, true><<<GE, 256, SMEM_BYTES>>>(h3, nullptr, 0, nullptr,
                                               Whi + 5 * H * H, Wlo + 5 * H * H, t3, NE, 3, 4);
    finalize_k<<<1, 128>>>(4, g3b, b3b, 1.0f / NE);
    bnout_k<<<(NE * H / 4 + 255) / 256, 256>>>(t3, 4, edge_out, NE * H / 4);
}

// round 8
// speedup vs baseline: 1.5522x; 1.3270x over previous
#include <cuda_runtime.h>
#include <cuda_bf16.h>
#include <cstdint>

#define H 128
#define NN 100000
#define NE 400000
#define NI 800000
#define BN_EPS 1e-5f

// ---------------- scratch ----------------
__device__ float g_P[NN * H];
__device__ float g_Q[NE * H];
__device__ float g_cat[NE * 2 * H];
__device__ float g_lvl[NN * H];
__device__ float g_h2[NN * H];
__device__ float g_t2[NN * H];
__device__ float g_h3[NE * H];
__device__ float g_t3[NE * H];
__device__ double g_sum[5][H];
__device__ double g_sq[5][H];
__device__ float g_scale[5][H];
__device__ float g_shift[5][H];
// Preconverted weights: [n][k] bf16, 16B-granule XOR swizzle pre-applied.
__device__ __nv_bfloat16 g_Whi[6][H * H];
__device__ __nv_bfloat16 g_Wlo[6][H * H];

// ---------------- helpers ----------------
__device__ __forceinline__ uint32_t smem_u32(const void* p) {
    uint32_t a;
    asm("{ .reg .u64 t; cvta.to.shared.u64 t, %1; cvt.u32.u64 %0, t; }" : "=r"(a) : "l"(p));
    return a;
}
__device__ __forceinline__ void ldsm_x4(uint32_t r[4], uint32_t a) {
    asm volatile("ldmatrix.sync.aligned.m8n8.x4.shared.b16 {%0,%1,%2,%3}, [%4];"
                 : "=r"(r[0]), "=r"(r[1]), "=r"(r[2]), "=r"(r[3]) : "r"(a));
}
__device__ __forceinline__ void mma16816(float c[4], const uint32_t a[4], const uint32_t b[2]) {
    asm volatile("mma.sync.aligned.m16n8k16.row.col.f32.bf16.bf16.f32 "
                 "{%0,%1,%2,%3}, {%4,%5,%6,%7}, {%8,%9}, {%0,%1,%2,%3};"
                 : "+f"(c[0]), "+f"(c[1]), "+f"(c[2]), "+f"(c[3])
                 : "r"(a[0]), "r"(a[1]), "r"(a[2]), "r"(a[3]), "r"(b[0]), "r"(b[1]));
}
__device__ __forceinline__ void red4(float* p, float4 v) {
    asm volatile("red.global.add.v4.f32 [%0], {%1,%2,%3,%4};"
                 :: "l"(p), "f"(v.x), "f"(v.y), "f"(v.z), "f"(v.w) : "memory");
}
__device__ __forceinline__ float relu_aff(float x, float sc, float sh) {
    return fmaxf(fmaf(x, sc, sh), 0.f);
}

// ---------------- zero init ----------------
__global__ void __launch_bounds__(256) zero_k() {
    size_t gid = (size_t)blockIdx.x * blockDim.x + threadIdx.x;
    const size_t n_cat4 = (size_t)NE * 2 * H / 4;
    const size_t n_lvl4 = (size_t)NN * H / 4;
    float4 z = make_float4(0.f, 0.f, 0.f, 0.f);
    if (gid < n_cat4)               ((float4*)g_cat)[gid] = z;
    else if (gid < n_cat4 + n_lvl4) ((float4*)g_lvl)[gid - n_cat4] = z;
    if (gid < 5 * H) {
        (&g_sum[0][0])[gid] = 0.0;
        (&g_sq[0][0])[gid] = 0.0;
    }
}

// ---------------- preconvert weights: W[k][n] -> hi/lo bf16 [n][k], pre-swizzled ----------------
__global__ void __launch_bounds__(256)
wconv_k(const float* __restrict__ W1, const float* __restrict__ W2a,
        const float* __restrict__ W2b, const float* __restrict__ W3a,
        const float* __restrict__ W3b)
{
    int m = blockIdx.x >> 3;
    int slice = blockIdx.x & 7;
    const float* src;
    switch (m) {
        case 0: src = W1; break;
        case 1: src = W1 + H * H; break;
        case 2: src = W2a; break;
        case 3: src = W2b; break;
        case 4: src = W3a; break;
        default: src = W3b; break;
    }
    int base = slice * 2048;
    for (int t = threadIdx.x; t < 2048; t += 256) {
        int idx = base + t;
        int n = idx >> 7, k = idx & 127;
        float v = src[k * H + n];
        uint32_t uv = __float_as_uint(v);
        uint32_t hb = uv & 0xFFFF0000u;
        float res = v - __uint_as_float(hb);
        uint32_t off = (uint32_t)n * 128u + ((((uint32_t)k >> 3) ^ ((uint32_t)n & 7)) << 3)
                     + ((uint32_t)k & 7);
        g_Whi[m][off] = __ushort_as_bfloat16((unsigned short)(hb >> 16));
        g_Wlo[m][off] = __float2bfloat16(res);
    }
}

// ---------------- mma.sync GEMM: C[M,128] = A[M,128] @ W, 3-way bf16 split ----------------
// CTA tile M=64, 256 threads (8 warps), warp tile 16 rows x 64 cols.
// smem 97KB -> 2 CTAs/SM.
// AMODE 0: A = A1
// AMODE 1: A = (1+*epsp)*A1 + A2 (row stride lda2)
// AMODE 2: A = relu(A1*scale[inSet] + shift[inSet])
// STATS : fused per-column sum/sumsq of C into g_sum/g_sq[statSet]
#define SMA_HI 0
#define SMA_LO 16384
#define SMW_HI 32768
#define SMW_LO 65536
#define SM_RED 98304
#define SMEM_BYTES (98304 + 1024)

template <int AMODE, bool STATS>
__global__ void __launch_bounds__(256)
gemm_mma(const float* __restrict__ A1, const float* __restrict__ A2, int lda2,
         const float* __restrict__ epsp,
         const __nv_bfloat16* __restrict__ Whi, const __nv_bfloat16* __restrict__ Wlo,
         float* __restrict__ C, int M, int inSet, int statSet)
{
    extern __shared__ char smem[];
    uint32_t sb = smem_u32(smem);
    const int tid = threadIdx.x;
    const int lane = tid & 31;
    const int wid = tid >> 5;

    // copy pre-swizzled W images (32KB each, hi+lo)
    {
        const uint4* shi = (const uint4*)Whi;
        const uint4* slo = (const uint4*)Wlo;
        uint4* dhi = (uint4*)(smem + SMW_HI);
        uint4* dlo = (uint4*)(smem + SMW_LO);
#pragma unroll
        for (int i = 0; i < 8; i++) {
            dhi[tid + i * 256] = shi[tid + i * 256];
            dlo[tid + i * 256] = slo[tid + i * 256];
        }
    }

    // load A rows (64 x 128), apply AMODE transform, split hi/lo, store swizzled
    {
        const int r = tid >> 2;            // 0..63
        const int cq = tid & 3;            // column quarter (32 cols)
        const int arow = blockIdx.x * 64 + r;
        const bool valid = arow < M;
        float alpha = 0.f;
        if (AMODE == 1) alpha = 1.0f + __ldg(epsp);
        const float* a1p = A1 + (size_t)arow * H + cq * 32;
        const float* a2p = (AMODE == 1) ? (A2 + (size_t)arow * lda2 + cq * 32) : nullptr;
#pragma unroll
        for (int g = 0; g < 4; g++) {
            float f[8];
            if (valid) {
                float4 u0 = *(const float4*)(a1p + g * 8);
                float4 u1 = *(const float4*)(a1p + g * 8 + 4);
                f[0] = u0.x; f[1] = u0.y; f[2] = u0.z; f[3] = u0.w;
                f[4] = u1.x; f[5] = u1.y; f[6] = u1.z; f[7] = u1.w;
                if (AMODE == 1) {
                    float4 w0 = *(const float4*)(a2p + g * 8);
                    float4 w1 = *(const float4*)(a2p + g * 8 + 4);
                    f[0] = fmaf(alpha, f[0], w0.x); f[1] = fmaf(alpha, f[1], w0.y);
                    f[2] = fmaf(alpha, f[2], w0.z); f[3] = fmaf(alpha, f[3], w0.w);
                    f[4] = fmaf(alpha, f[4], w1.x); f[5] = fmaf(alpha, f[5], w1.y);
                    f[6] = fmaf(alpha, f[6], w1.z); f[7] = fmaf(alpha, f[7], w1.w);
                } else if (AMODE == 2) {
                    int c0 = cq * 32 + g * 8;
#pragma unroll
                    for (int j = 0; j < 8; j++)
                        f[j] = relu_aff(f[j], g_scale[inSet][c0 + j], g_shift[inSet][c0 + j]);
                }
            } else {
#pragma unroll
                for (int j = 0; j < 8; j++) f[j] = 0.f;
            }
            uint32_t hv[4], lv[4];
#pragma unroll
            for (int j = 0; j < 4; j++) {
                float a = f[2 * j], b = f[2 * j + 1];
                uint32_t ua = __float_as_uint(a), ub = __float_as_uint(b);
                hv[j] = __byte_perm(ua, ub, 0x7632);
                float ra = a - __uint_as_float(ua & 0xFFFF0000u);
                float rb = b - __uint_as_float(ub & 0xFFFF0000u);
                __nv_bfloat162 lo2 = __floats2bfloat162_rn(ra, rb);
                lv[j] = *(uint32_t*)&lo2;
            }
            uint32_t gran = (uint32_t)((cq * 4 + g) ^ (r & 7));
            uint32_t off = (uint32_t)r * 256u + gran * 16u;
            *(uint4*)(smem + SMA_HI + off) = make_uint4(hv[0], hv[1], hv[2], hv[3]);
            *(uint4*)(smem + SMA_LO + off) = make_uint4(lv[0], lv[1], lv[2], lv[3]);
        }
    }
    if (STATS) ((float*)(smem + SM_RED))[tid] = 0.f;  // 256 floats: sum[128] | sq[128]
    __syncthreads();

    const int wm = wid & 3;       // row block (16 rows)
    const int wn = wid >> 2;      // col block (64 cols)
    const int rb = wm * 16;
    const int cbc = wn * 64;

    float acc[8][4];
#pragma unroll
    for (int j = 0; j < 8; j++)
#pragma unroll
        for (int q = 0; q < 4; q++) acc[j][q] = 0.f;

#pragma unroll
    for (int ks = 0; ks < 8; ks++) {
        const uint32_t kg = (uint32_t)ks * 2u;
        // A fragments: one m16k16 tile, hi + lo
        uint32_t ahi[4], alo[4];
        {
            uint32_t rowA = (uint32_t)(rb + (lane & 15));
            uint32_t gran = (kg + (uint32_t)(lane >> 4)) ^ (rowA & 7u);
            uint32_t a = sb + SMA_HI + rowA * 256u + gran * 16u;
            ldsm_x4(ahi, a);
            ldsm_x4(alo, a + 16384u);
        }
        // B fragments: paired-j x4 loads (two n8k16 fragments per ldsm)
#pragma unroll
        for (int jp = 0; jp < 4; jp++) {
            uint32_t rowB = (uint32_t)(cbc + jp * 16 + ((lane >> 4) << 3) + (lane & 7));
            uint32_t kgr = kg + (uint32_t)((lane >> 3) & 1);
            uint32_t b = sb + SMW_HI + rowB * 256u + ((kgr ^ (rowB & 7u)) * 16u);
            uint32_t bh[4], bl[4];
            ldsm_x4(bh, b);
            ldsm_x4(bl, b + 32768u);
            mma16816(acc[jp * 2],     ahi, bh);
            mma16816(acc[jp * 2],     ahi, bl + 0);   // placeholder to keep layout clear
            mma16816(acc[jp * 2],     alo, bh);
            mma16816(acc[jp * 2 + 1], ahi, bh + 2);
            mma16816(acc[jp * 2 + 1], ahi, bl + 2);
            mma16816(acc[jp * 2 + 1], alo, bh + 2);
        }
    }

    // epilogue: direct global stores (float2 per fragment row)
    const int gq = lane >> 2, rq = lane & 3;
    {
        int r0 = blockIdx.x * 64 + rb + gq;
#pragma unroll
        for (int j = 0; j < 8; j++) {
            int col = cbc + j * 8 + rq * 2;
            if (r0 < M)
                *(float2*)(C + (size_t)r0 * H + col) = make_float2(acc[j][0], acc[j][1]);
            if (r0 + 8 < M)
                *(float2*)(C + (size_t)(r0 + 8) * H + col) = make_float2(acc[j][2], acc[j][3]);
        }
    }

    if (STATS) {
        float* s_sum = (float*)(smem + SM_RED);
        float* s_sq  = s_sum + 128;
#pragma unroll
        for (int j = 0; j < 8; j++) {
            float c0 = acc[j][0], c1 = acc[j][1], c2 = acc[j][2], c3 = acc[j][3];
            float se = c0 + c2, so = c1 + c3;
            float qe = fmaf(c0, c0, c2 * c2);
            float qo = fmaf(c1, c1, c3 * c3);
#pragma unroll
            for (int o = 16; o >= 4; o >>= 1) {
                se += __shfl_down_sync(0xFFFFFFFFu, se, o);
                so += __shfl_down_sync(0xFFFFFFFFu, so, o);
                qe += __shfl_down_sync(0xFFFFFFFFu, qe, o);
                qo += __shfl_down_sync(0xFFFFFFFFu, qo, o);
            }
            if (lane < 4) {
                int col = cbc + j * 8 + lane * 2;
                atomicAdd(&s_sum[col],     se);
                atomicAdd(&s_sum[col + 1], so);
                atomicAdd(&s_sq[col],      qe);
                atomicAdd(&s_sq[col + 1],  qo);
            }
        }
        __syncthreads();
        if (tid < 128)      atomicAdd(&g_sum[statSet][tid],       (double)s_sum[tid]);
        else                atomicAdd(&g_sq[statSet][tid - 128],  (double)s_sq[tid - 128]);
    }
}

// ---------------- stats over msg_raw[i] = P[n_i] + Q[e_i] ----------------
__global__ void __launch_bounds__(256)
stats_msg_k(const int* __restrict__ node_idx, const int* __restrict__ edge_idx)
{
    const int lane = threadIdx.x & 31;
    const int w = threadIdx.x >> 5;
    const int c4 = lane << 2;
    float4 s = make_float4(0.f, 0.f, 0.f, 0.f);
    float4 q = make_float4(0.f, 0.f, 0.f, 0.f);
    for (int i = blockIdx.x * 8 + w; i < NI; i += gridDim.x * 8) {
        int n = node_idx[i], e = edge_idx[i];
        float4 p  = *(const float4*)(g_P + (size_t)n * H + c4);
        float4 qq = *(const float4*)(g_Q + (size_t)e * H + c4);
        float vx = p.x + qq.x, vy = p.y + qq.y, vz = p.z + qq.z, vw = p.w + qq.w;
        s.x += vx; s.y += vy; s.z += vz; s.w += vw;
        q.x = fmaf(vx, vx, q.x); q.y = fmaf(vy, vy, q.y);
        q.z = fmaf(vz, vz, q.z); q.w = fmaf(vw, vw, q.w);
    }
    __shared__ float red[8][128];
    red[w][c4 + 0] = s.x; red[w][c4 + 1] = s.y; red[w][c4 + 2] = s.z; red[w][c4 + 3] = s.w;
    __syncthreads();
    if (threadIdx.x < 128) {
        float t = 0.f;
#pragma unroll
        for (int r = 0; r < 8; r++) t += red[r][threadIdx.x];
        atomicAdd(&g_sum[0][threadIdx.x], (double)t);
    }
    __syncthreads();
    red[w][c4 + 0] = q.x; red[w][c4 + 1] = q.y; red[w][c4 + 2] = q.z; red[w][c4 + 3] = q.w;
    __syncthreads();
    if (threadIdx.x < 128) {
        float t = 0.f;
#pragma unroll
        for (int r = 0; r < 8; r++) t += red[r][threadIdx.x];
        atomicAdd(&g_sq[0][threadIdx.x], (double)t);
    }
}

// ---------------- finalize BN stats ----------------
__global__ void finalize_k(int set, const float* __restrict__ g,
                           const float* __restrict__ b, float invN)
{
    int j = threadIdx.x;
    double mean = g_sum[set][j] * (double)invN;
    double var = g_sq[set][j] * (double)invN - mean * mean;
    float sc = g[j] * rsqrtf((float)var + BN_EPS);
    g_scale[set][j] = sc;
    g_shift[set][j] = fmaf(-(float)mean, sc, b[j]);
}

// ---------------- segment scatter kernels ----------------
__global__ void __launch_bounds__(256)
cat_k(const float* __restrict__ node_rep,
      const int* __restrict__ node_idx, const int* __restrict__ edge_idx)
{
    const int lane = threadIdx.x & 31;
    const int w = threadIdx.x >> 5;
    const int c4 = lane << 2;
    int i = blockIdx.x * 8 + w;
    if (i >= NI) return;
    int n = node_idx[i], e = edge_idx[i];
    float4 p = *(const float4*)(g_P + (size_t)n * H + c4);
    float4 q = *(const float4*)(g_Q + (size_t)e * H + c4);
    float4 sc = *(const float4*)&g_scale[0][c4];
    float4 sh = *(const float4*)&g_shift[0][c4];
    float4 m;
    m.x = relu_aff(p.x + q.x, sc.x, sh.x);
    m.y = relu_aff(p.y + q.y, sc.y, sh.y);
    m.z = relu_aff(p.z + q.z, sc.z, sh.z);
    m.w = relu_aff(p.w + q.w, sc.w, sh.w);
    red4(g_cat + (size_t)e * (2 * H) + c4, m);
    float4 nr = *(const float4*)(node_rep + (size_t)n * H + c4);
    red4(g_cat + (size_t)e * (2 * H) + H + c4, nr);
}

__global__ void __launch_bounds__(256)
lvl_k(const int* __restrict__ node_idx, const int* __restrict__ edge_idx)
{
    const int lane = threadIdx.x & 31;
    const int w = threadIdx.x >> 5;
    const int c4 = lane << 2;
    int i = blockIdx.x * 8 + w;
    if (i >= NI) return;
    int n = node_idx[i], e = edge_idx[i];
    float4 p = *(const float4*)(g_P + (size_t)n * H + c4);
    float4 q = *(const float4*)(g_Q + (size_t)e * H + c4);
    float4 sc = *(const float4*)&g_scale[0][c4];
    float4 sh = *(const float4*)&g_shift[0][c4];
    float4 cv = *(const float4*)(g_cat + (size_t)e * (2 * H) + c4);
    float4 d;
    d.x = cv.x - relu_aff(p.x + q.x, sc.x, sh.x);
    d.y = cv.y - relu_aff(p.y + q.y, sc.y, sh.y);
    d.z = cv.z - relu_aff(p.z + q.z, sc.z, sh.z);
    d.w = cv.w - relu_aff(p.w + q.w, sc.w, sh.w);
    red4(g_lvl + (size_t)n * H + c4, d);
}

// ---------------- final elementwise bn_relu ----------------
__global__ void __launch_bounds__(256)
bnout_k(const float* __restrict__ in, int set, float* __restrict__ out, int n4)
{
    int t = blockIdx.x * blockDim.x + threadIdx.x;
    if (t >= n4) return;
    int c4 = (t & 31) << 2;
    float4 v = ((const float4*)in)[t];
    float4 sc = *(const float4*)&g_scale[set][c4];
    float4 sh = *(const float4*)&g_shift[set][c4];
    float4 o;
    o.x = relu_aff(v.x, sc.x, sh.x);
    o.y = relu_aff(v.y, sc.y, sh.y);
    o.z = relu_aff(v.z, sc.z, sh.z);
    o.w = relu_aff(v.w, sc.w, sh.w);
    ((float4*)out)[t] = o;
}

// ---------------- launch ----------------
extern "C" void kernel_launch(void* const* d_in, const int* in_sizes, int n_in,
                              void* d_out, int out_size)
{
    const float* node_rep = (const float*)d_in[0];
    const float* edge_rep = (const float*)d_in[1];
    const int*   node_idx = (const int*)d_in[2];
    const int*   edge_idx = (const int*)d_in[3];
    const float* W1  = (const float*)d_in[4];
    const float* g1  = (const float*)d_in[5];
    const float* b1  = (const float*)d_in[6];
    const float* W2a = (const float*)d_in[7];
    const float* g2a = (const float*)d_in[8];
    const float* b2a = (const float*)d_in[9];
    const float* W2b = (const float*)d_in[10];
    const float* g2b = (const float*)d_in[11];
    const float* b2b = (const float*)d_in[12];
    const float* W3a = (const float*)d_in[13];
    const float* g3a = (const float*)d_in[14];
    const float* b3a = (const float*)d_in[15];
    const float* W3b = (const float*)d_in[16];
    const float* g3b = (const float*)d_in[17];
    const float* b3b = (const float*)d_in[18];
    const float* eps1 = (const float*)d_in[19];
    const float* eps2 = (const float*)d_in[20];

    float *P, *Q, *cat, *lvl, *h2, *t2, *h3, *t3;
    __nv_bfloat16 *Whi, *Wlo;
    cudaGetSymbolAddress((void**)&P,   g_P);
    cudaGetSymbolAddress((void**)&Q,   g_Q);
    cudaGetSymbolAddress((void**)&cat, g_cat);
    cudaGetSymbolAddress((void**)&lvl, g_lvl);
    cudaGetSymbolAddress((void**)&h2,  g_h2);
    cudaGetSymbolAddress((void**)&t2,  g_t2);
    cudaGetSymbolAddress((void**)&h3,  g_h3);
    cudaGetSymbolAddress((void**)&t3,  g_t3);
    cudaGetSymbolAddress((void**)&Whi, g_Whi);
    cudaGetSymbolAddress((void**)&Wlo, g_Wlo);

    cudaFuncSetAttribute(gemm_mma<0, false>, cudaFuncAttributeMaxDynamicSharedMemorySize, SMEM_BYTES);
    cudaFuncSetAttribute(gemm_mma<1, true>,  cudaFuncAttributeMaxDynamicSharedMemorySize, SMEM_BYTES);
    cudaFuncSetAttribute(gemm_mma<2, true>,  cudaFuncAttributeMaxDynamicSharedMemorySize, SMEM_BYTES);

    float* node_out = (float*)d_out;
    float* edge_out = (float*)d_out + (size_t)NN * H;

    const int GN = (NN + 63) / 64;   // 1563
    const int GE = (NE + 63) / 64;   // 6250

    zero_k<<<112500, 256>>>();
    wconv_k<<<48, 256>>>(W1, W2a, W2b, W3a, W3b);

    // P = node_rep @ W1[:128], Q = edge_rep @ W1[128:]
    gemm_mma<0, false><<<GN, 256, SMEM_BYTES>>>(node_rep, nullptr, 0, nullptr,
                                                Whi + 0 * H * H, Wlo + 0 * H * H, P, NN, 0, 0);
    gemm_mma<0, false><<<GE, 256, SMEM_BYTES>>>(edge_rep, nullptr, 0, nullptr,
                                                Whi + 1 * H * H, Wlo + 1 * H * H, Q, NE, 0, 0);

    stats_msg_k<<<1184, 256>>>(node_idx, edge_idx);
    finalize_k<<<1, 128>>>(0, g1, b1, 1.0f / NI);

    cat_k<<<NI / 8, 256>>>(node_rep, node_idx, edge_idx);
    lvl_k<<<NI / 8, 256>>>(node_idx, edge_idx);

    // node path
    gemm_mma<1, true><<<GN, 256, SMEM_BYTES>>>(node_rep, lvl, H, eps1,
                                               Whi + 2 * H * H, Wlo + 2 * H * H, h2, NN, 0, 1);
    finalize_k<<<1, 128>>>(1, g2a, b2a, 1.0f / NN);
    gemm_mma<2, true><<<GN, 256, SMEM_BYTES>>>(h2, nullptr, 0, nullptr,
                                               Whi + 3 * H * H, Wlo + 3 * H * H, t2, NN, 1, 2);
    finalize_k<<<1, 128>>>(2, g2b, b2b, 1.0f / NN);
    bnout_k<<<(NN * H / 4 + 255) / 256, 256>>>(t2, 2, node_out, NN * H / 4);

    // edge path
    gemm_mma<1, true><<<GE, 256, SMEM_BYTES>>>(edge_rep, cat + H, 2 * H, eps2,
                                               Whi + 4 * H * H, Wlo + 4 * H * H, h3, NE, 0, 3);
    finalize_k<<<1, 128>>>(3, g3a, b3a, 1.0f / NE);
    gemm_mma<2, true><<<GE, 256, SMEM_BYTES>>>(h3, nullptr, 0, nullptr,
                                               Whi + 5 * H * H, Wlo + 5 * H * H, t3, NE, 3, 4);
    finalize_k<<<1, 128>>>(4, g3b, b3b, 1.0f / NE);
    bnout_k<<<(NE * H / 4 + 255) / 256, 256>>>(t3, 4, edge_out, NE * H / 4);
}

// round 12
// speedup vs baseline: 1.6124x; 1.0388x over previous
#include <cuda_runtime.h>
#include <cuda_bf16.h>
#include <cstdint>

#define H 128
#define NN 100000
#define NE 400000
#define NI 800000
#define BN_EPS 1e-5f
#define TPC 4   // GEMM M-tiles per CTA

// ---------------- scratch ----------------
__device__ float g_P[NN * H];
__device__ float g_Q[NE * H];
__device__ float g_cat[NE * 2 * H];
__device__ float g_lvl[NN * H];
__device__ float g_h2[NN * H];
__device__ float g_t2[NN * H];
__device__ float g_h3[NE * H];
__device__ float g_t3[NE * H];
__device__ double g_sum[5][H];
__device__ double g_sq[5][H];
__device__ float g_scale[5][H];
__device__ float g_shift[5][H];
// Preconverted weights: [n][k] bf16, 16B-granule XOR swizzle pre-applied.
__device__ __nv_bfloat16 g_Whi[6][H * H];
__device__ __nv_bfloat16 g_Wlo[6][H * H];

// ---------------- helpers ----------------
__device__ __forceinline__ uint32_t smem_u32(const void* p) {
    uint32_t a;
    asm("{ .reg .u64 t; cvta.to.shared.u64 t, %1; cvt.u32.u64 %0, t; }" : "=r"(a) : "l"(p));
    return a;
}
__device__ __forceinline__ void ldsm_x4(uint32_t r[4], uint32_t a) {
    asm volatile("ldmatrix.sync.aligned.m8n8.x4.shared.b16 {%0,%1,%2,%3}, [%4];"
                 : "=r"(r[0]), "=r"(r[1]), "=r"(r[2]), "=r"(r[3]) : "r"(a));
}
__device__ __forceinline__ void mma16816(float c[4], const uint32_t a[4], const uint32_t b[2]) {
    asm volatile("mma.sync.aligned.m16n8k16.row.col.f32.bf16.bf16.f32 "
                 "{%0,%1,%2,%3}, {%4,%5,%6,%7}, {%8,%9}, {%0,%1,%2,%3};"
                 : "+f"(c[0]), "+f"(c[1]), "+f"(c[2]), "+f"(c[3])
                 : "r"(a[0]), "r"(a[1]), "r"(a[2]), "r"(a[3]), "r"(b[0]), "r"(b[1]));
}
__device__ __forceinline__ void red4(float* p, float4 v) {
    asm volatile("red.global.add.v4.f32 [%0], {%1,%2,%3,%4};"
                 :: "l"(p), "f"(v.x), "f"(v.y), "f"(v.z), "f"(v.w) : "memory");
}
__device__ __forceinline__ float relu_aff(float x, float sc, float sh) {
    return fmaxf(fmaf(x, sc, sh), 0.f);
}

// ---------------- zero init ----------------
__global__ void __launch_bounds__(256) zero_k() {
    size_t gid = (size_t)blockIdx.x * blockDim.x + threadIdx.x;
    const size_t n_cat4 = (size_t)NE * 2 * H / 4;
    const size_t n_lvl4 = (size_t)NN * H / 4;
    float4 z = make_float4(0.f, 0.f, 0.f, 0.f);
    if (gid < n_cat4)               ((float4*)g_cat)[gid] = z;
    else if (gid < n_cat4 + n_lvl4) ((float4*)g_lvl)[gid - n_cat4] = z;
    if (gid < 5 * H) {
        (&g_sum[0][0])[gid] = 0.0;
        (&g_sq[0][0])[gid] = 0.0;
    }
}

// ---------------- preconvert weights: W[k][n] -> hi/lo bf16 [n][k], pre-swizzled ----------------
__global__ void __launch_bounds__(256)
wconv_k(const float* __restrict__ W1, const float* __restrict__ W2a,
        const float* __restrict__ W2b, const float* __restrict__ W3a,
        const float* __restrict__ W3b)
{
    int m = blockIdx.x >> 3;
    int slice = blockIdx.x & 7;
    const float* src;
    switch (m) {
        case 0: src = W1; break;
        case 1: src = W1 + H * H; break;
        case 2: src = W2a; break;
        case 3: src = W2b; break;
        case 4: src = W3a; break;
        default: src = W3b; break;
    }
    int base = slice * 2048;
    for (int t = threadIdx.x; t < 2048; t += 256) {
        int idx = base + t;
        int n = idx >> 7, k = idx & 127;
        float v = src[k * H + n];
        uint32_t uv = __float_as_uint(v);
        uint32_t hb = uv & 0xFFFF0000u;
        float res = v - __uint_as_float(hb);
        uint32_t off = (uint32_t)n * 128u + ((((uint32_t)k >> 3) ^ ((uint32_t)n & 7)) << 3)
                     + ((uint32_t)k & 7);
        g_Whi[m][off] = __ushort_as_bfloat16((unsigned short)(hb >> 16));
        g_Wlo[m][off] = __float2bfloat16(res);
    }
}

// ---------------- mma.sync GEMM: C[M,128] = A[M,128] @ W, 3-way bf16 split ----------------
// CTA: 256 threads, processes TPC M-tiles of 64 rows. Warp tile 32 rows x 32 cols
// (2 row-groups x 4 col-groups) -> B ldmatrix redundancy 2x (was 4x).
// W (hi+lo, 64KB) loaded to smem ONCE per CTA, amortized over TPC tiles.
// smem 97KB -> 2 CTAs/SM.
#define SMW_HI 0
#define SMW_LO 32768
#define SMA_HI 65536
#define SMA_LO 81920
#define SM_RED 98304
#define SMEM_BYTES (98304 + 1024)

template <int AMODE, bool STATS>
__global__ void __launch_bounds__(256)
gemm_mma(const float* __restrict__ A1, const float* __restrict__ A2, int lda2,
         const float* __restrict__ epsp,
         const __nv_bfloat16* __restrict__ Whi, const __nv_bfloat16* __restrict__ Wlo,
         float* __restrict__ C, int M, int inSet, int statSet)
{
    extern __shared__ char smem[];
    uint32_t sb = smem_u32(smem);
    const int tid = threadIdx.x;
    const int lane = tid & 31;
    const int wid = tid >> 5;

    // W images (32KB hi + 32KB lo), once per CTA
    {
        const uint4* shi = (const uint4*)Whi;
        const uint4* slo = (const uint4*)Wlo;
        uint4* dhi = (uint4*)(smem + SMW_HI);
        uint4* dlo = (uint4*)(smem + SMW_LO);
#pragma unroll
        for (int i = 0; i < 8; i++) {
            dhi[tid + i * 256] = shi[tid + i * 256];
            dlo[tid + i * 256] = slo[tid + i * 256];
        }
    }
    if (STATS) ((float*)(smem + SM_RED))[tid] = 0.f;  // sum[128] | sq[128]

    float alpha = 0.f;
    if (AMODE == 1) alpha = 1.0f + __ldg(epsp);

    const int wm = wid & 1;        // row group (32 rows)
    const int wn = wid >> 1;       // col group (32 cols)
    const int rb = wm * 32;
    const int cbc = wn * 32;
    const int gq = lane >> 2, rq = lane & 3;

    for (int t = 0; t < TPC; t++) {
        const int row0 = (blockIdx.x * TPC + t) * 64;
        if (row0 >= M) break;
        __syncthreads();   // previous tile's readers done before overwriting A

        // load A rows (64 x 128), transform, split hi/lo, store swizzled
        {
            const int r = tid >> 2;
            const int cq = tid & 3;
            const int arow = row0 + r;
            const bool valid = arow < M;
            const float* a1p = A1 + (size_t)arow * H + cq * 32;
            const float* a2p = (AMODE == 1) ? (A2 + (size_t)arow * lda2 + cq * 32) : nullptr;
#pragma unroll
            for (int g = 0; g < 4; g++) {
                float f[8];
                if (valid) {
                    float4 u0 = *(const float4*)(a1p + g * 8);
                    float4 u1 = *(const float4*)(a1p + g * 8 + 4);
                    f[0] = u0.x; f[1] = u0.y; f[2] = u0.z; f[3] = u0.w;
                    f[4] = u1.x; f[5] = u1.y; f[6] = u1.z; f[7] = u1.w;
                    if (AMODE == 1) {
                        float4 w0 = *(const float4*)(a2p + g * 8);
                        float4 w1 = *(const float4*)(a2p + g * 8 + 4);
                        f[0] = fmaf(alpha, f[0], w0.x); f[1] = fmaf(alpha, f[1], w0.y);
                        f[2] = fmaf(alpha, f[2], w0.z); f[3] = fmaf(alpha, f[3], w0.w);
                        f[4] = fmaf(alpha, f[4], w1.x); f[5] = fmaf(alpha, f[5], w1.y);
                        f[6] = fmaf(alpha, f[6], w1.z); f[7] = fmaf(alpha, f[7], w1.w);
                    } else if (AMODE == 2) {
                        int c0 = cq * 32 + g * 8;
#pragma unroll
                        for (int j = 0; j < 8; j++)
                            f[j] = relu_aff(f[j], g_scale[inSet][c0 + j], g_shift[inSet][c0 + j]);
                    }
                } else {
#pragma unroll
                    for (int j = 0; j < 8; j++) f[j] = 0.f;
                }
                uint32_t hv[4], lv[4];
#pragma unroll
                for (int j = 0; j < 4; j++) {
                    float a = f[2 * j], b = f[2 * j + 1];
                    uint32_t ua = __float_as_uint(a), ub = __float_as_uint(b);
                    hv[j] = __byte_perm(ua, ub, 0x7632);
                    float ra = a - __uint_as_float(ua & 0xFFFF0000u);
                    float rb2 = b - __uint_as_float(ub & 0xFFFF0000u);
                    __nv_bfloat162 lo2 = __floats2bfloat162_rn(ra, rb2);
                    lv[j] = *(uint32_t*)&lo2;
                }
                uint32_t gran = (uint32_t)((cq * 4 + g) ^ (r & 7));
                uint32_t off = (uint32_t)r * 256u + gran * 16u;
                *(uint4*)(smem + SMA_HI + off) = make_uint4(hv[0], hv[1], hv[2], hv[3]);
                *(uint4*)(smem + SMA_LO + off) = make_uint4(lv[0], lv[1], lv[2], lv[3]);
            }
        }
        __syncthreads();

        float acc[2][4][4];
#pragma unroll
        for (int mt = 0; mt < 2; mt++)
#pragma unroll
            for (int j = 0; j < 4; j++)
#pragma unroll
                for (int q = 0; q < 4; q++) acc[mt][j][q] = 0.f;

#pragma unroll
        for (int ks = 0; ks < 8; ks++) {
            const uint32_t kg = (uint32_t)ks * 2u;
            uint32_t ahi[2][4], alo[2][4];
#pragma unroll
            for (int mt = 0; mt < 2; mt++) {
                uint32_t rowA = (uint32_t)(rb + mt * 16 + (lane & 15));
                uint32_t gran = (kg + (uint32_t)(lane >> 4)) ^ (rowA & 7u);
                uint32_t a = sb + SMA_HI + rowA * 256u + gran * 16u;
                ldsm_x4(ahi[mt], a);
                ldsm_x4(alo[mt], a + 16384u);
            }
#pragma unroll
            for (int pr = 0; pr < 2; pr++) {
                uint32_t rowB = (uint32_t)(cbc + pr * 16 + ((lane >> 4) << 3) + (lane & 7));
                uint32_t kgr = kg + (uint32_t)((lane >> 3) & 1);
                uint32_t b = sb + SMW_HI + rowB * 256u + ((kgr ^ (rowB & 7u)) * 16u);
                uint32_t bh[4], bl[4];
                ldsm_x4(bh, b);
                ldsm_x4(bl, b + 32768u);
#pragma unroll
                for (int mt = 0; mt < 2; mt++) {
                    mma16816(acc[mt][pr * 2],     ahi[mt], bh);
                    mma16816(acc[mt][pr * 2],     ahi[mt], bl);
                    mma16816(acc[mt][pr * 2],     alo[mt], bh);
                    mma16816(acc[mt][pr * 2 + 1], ahi[mt], bh + 2);
                    mma16816(acc[mt][pr * 2 + 1], ahi[mt], bl + 2);
                    mma16816(acc[mt][pr * 2 + 1], alo[mt], bh + 2);
                }
            }
        }

        // epilogue: global stores
#pragma unroll
        for (int mt = 0; mt < 2; mt++) {
            int r0 = row0 + rb + mt * 16 + gq;
#pragma unroll
            for (int j = 0; j < 4; j++) {
                int col = cbc + j * 8 + rq * 2;
                if (r0 < M)
                    *(float2*)(C + (size_t)r0 * H + col) = make_float2(acc[mt][j][0], acc[mt][j][1]);
                if (r0 + 8 < M)
                    *(float2*)(C + (size_t)(r0 + 8) * H + col) = make_float2(acc[mt][j][2], acc[mt][j][3]);
            }
        }

        if (STATS) {
            float* s_sum = (float*)(smem + SM_RED);
            float* s_sq  = s_sum + 128;
#pragma unroll
            for (int j = 0; j < 4; j++) {
                float se = 0.f, so = 0.f, qe = 0.f, qo = 0.f;
#pragma unroll
                for (int mt = 0; mt < 2; mt++) {
                    float c0 = acc[mt][j][0], c1 = acc[mt][j][1];
                    float c2 = acc[mt][j][2], c3 = acc[mt][j][3];
                    se += c0 + c2; so += c1 + c3;
                    qe = fmaf(c0, c0, qe); qe = fmaf(c2, c2, qe);
                    qo = fmaf(c1, c1, qo); qo = fmaf(c3, c3, qo);
                }
#pragma unroll
                for (int o = 16; o >= 4; o >>= 1) {
                    se += __shfl_down_sync(0xFFFFFFFFu, se, o);
                    so += __shfl_down_sync(0xFFFFFFFFu, so, o);
                    qe += __shfl_down_sync(0xFFFFFFFFu, qe, o);
                    qo += __shfl_down_sync(0xFFFFFFFFu, qo, o);
                }
                if (lane < 4) {
                    int col = cbc + j * 8 + lane * 2;
                    atomicAdd(&s_sum[col],     se);
                    atomicAdd(&s_sum[col + 1], so);
                    atomicAdd(&s_sq[col],      qe);
                    atomicAdd(&s_sq[col + 1],  qo);
                }
            }
        }
    }

    if (STATS) {
        __syncthreads();
        float* s_sum = (float*)(smem + SM_RED);
        if (tid < 128)      atomicAdd(&g_sum[statSet][tid],       (double)s_sum[tid]);
        else                atomicAdd(&g_sq[statSet][tid - 128],  (double)s_sum[tid]);
    }
}

// ---------------- stats over msg_raw[i] = P[n_i] + Q[e_i] ----------------
__global__ void __launch_bounds__(256)
stats_msg_k(const int* __restrict__ node_idx, const int* __restrict__ edge_idx)
{
    const int lane = threadIdx.x & 31;
    const int w = threadIdx.x >> 5;
    const int c4 = lane << 2;
    float4 s = make_float4(0.f, 0.f, 0.f, 0.f);
    float4 q = make_float4(0.f, 0.f, 0.f, 0.f);
    for (int i = blockIdx.x * 8 + w; i < NI; i += gridDim.x * 8) {
        int n = node_idx[i], e = edge_idx[i];
        float4 p  = *(const float4*)(g_P + (size_t)n * H + c4);
        float4 qq = *(const float4*)(g_Q + (size_t)e * H + c4);
        float vx = p.x + qq.x, vy = p.y + qq.y, vz = p.z + qq.z, vw = p.w + qq.w;
        s.x += vx; s.y += vy; s.z += vz; s.w += vw;
        q.x = fmaf(vx, vx, q.x); q.y = fmaf(vy, vy, q.y);
        q.z = fmaf(vz, vz, q.z); q.w = fmaf(vw, vw, q.w);
    }
    __shared__ float red[8][128];
    red[w][c4 + 0] = s.x; red[w][c4 + 1] = s.y; red[w][c4 + 2] = s.z; red[w][c4 + 3] = s.w;
    __syncthreads();
    if (threadIdx.x < 128) {
        float t = 0.f;
#pragma unroll
        for (int r = 0; r < 8; r++) t += red[r][threadIdx.x];
        atomicAdd(&g_sum[0][threadIdx.x], (double)t);
    }
    __syncthreads();
    red[w][c4 + 0] = q.x; red[w][c4 + 1] = q.y; red[w][c4 + 2] = q.z; red[w][c4 + 3] = q.w;
    __syncthreads();
    if (threadIdx.x < 128) {
        float t = 0.f;
#pragma unroll
        for (int r = 0; r < 8; r++) t += red[r][threadIdx.x];
        atomicAdd(&g_sq[0][threadIdx.x], (double)t);
    }
}

// ---------------- finalize BN stats ----------------
__global__ void finalize_k(int set, const float* __restrict__ g,
                           const float* __restrict__ b, float invN)
{
    int j = threadIdx.x;
    double mean = g_sum[set][j] * (double)invN;
    double var = g_sq[set][j] * (double)invN - mean * mean;
    float sc = g[j] * rsqrtf((float)var + BN_EPS);
    g_scale[set][j] = sc;
    g_shift[set][j] = fmaf(-(float)mean, sc, b[j]);
}

// ---------------- cat pass: scatter msg/node_rep by edge, and -msg by node ----------------
__global__ void __launch_bounds__(256)
cat_k(const float* __restrict__ node_rep,
      const int* __restrict__ node_idx, const int* __restrict__ edge_idx)
{
    const int lane = threadIdx.x & 31;
    const int w = threadIdx.x >> 5;
    const int c4 = lane << 2;
    int i = blockIdx.x * 8 + w;
    if (i >= NI) return;
    int n = node_idx[i], e = edge_idx[i];
    float4 p = *(const float4*)(g_P + (size_t)n * H + c4);
    float4 q = *(const float4*)(g_Q + (size_t)e * H + c4);
    float4 sc = *(const float4*)&g_scale[0][c4];
    float4 sh = *(const float4*)&g_shift[0][c4];
    float4 m;
    m.x = relu_aff(p.x + q.x, sc.x, sh.x);
    m.y = relu_aff(p.y + q.y, sc.y, sh.y);
    m.z = relu_aff(p.z + q.z, sc.z, sh.z);
    m.w = relu_aff(p.w + q.w, sc.w, sh.w);
    red4(g_cat + (size_t)e * (2 * H) + c4, m);
    // lvl[n] -= msg_i  (other half added by lvl2_k after cat completes)
    red4(g_lvl + (size_t)n * H + c4, make_float4(-m.x, -m.y, -m.z, -m.w));
    float4 nr = *(const float4*)(node_rep + (size_t)n * H + c4);
    red4(g_cat + (size_t)e * (2 * H) + H + c4, nr);
}

// ---------------- lvl pass 2: lvl[n] += catm[e_i] (no P/Q re-gather) ----------------
__global__ void __launch_bounds__(256)
lvl2_k(const int* __restrict__ node_idx, const int* __restrict__ edge_idx)
{
    const int lane = threadIdx.x & 31;
    const int w = threadIdx.x >> 5;
    const int c4 = lane << 2;
    int i = blockIdx.x * 8 + w;
    if (i >= NI) return;
    int n = node_idx[i], e = edge_idx[i];
    float4 cv = *(const float4*)(g_cat + (size_t)e * (2 * H) + c4);
    red4(g_lvl + (size_t)n * H + c4, cv);
}

// ---------------- final elementwise bn_relu ----------------
__global__ void __launch_bounds__(256)
bnout_k(const float* __restrict__ in, int set, float* __restrict__ out, int n4)
{
    int t = blockIdx.x * blockDim.x + threadIdx.x;
    if (t >= n4) return;
    int c4 = (t & 31) << 2;
    float4 v = ((const float4*)in)[t];
    float4 sc = *(const float4*)&g_scale[set][c4];
    float4 sh = *(const float4*)&g_shift[set][c4];
    float4 o;
    o.x = relu_aff(v.x, sc.x, sh.x);
    o.y = relu_aff(v.y, sc.y, sh.y);
    o.z = relu_aff(v.z, sc.z, sh.z);
    o.w = relu_aff(v.w, sc.w, sh.w);
    ((float4*)out)[t] = o;
}

// ---------------- launch ----------------
extern "C" void kernel_launch(void* const* d_in, const int* in_sizes, int n_in,
                              void* d_out, int out_size)
{
    const float* node_rep = (const float*)d_in[0];
    const float* edge_rep = (const float*)d_in[1];
    const int*   node_idx = (const int*)d_in[2];
    const int*   edge_idx = (const int*)d_in[3];
    const float* W1  = (const float*)d_in[4];
    const float* g1  = (const float*)d_in[5];
    const float* b1  = (const float*)d_in[6];
    const float* W2a = (const float*)d_in[7];
    const float* g2a = (const float*)d_in[8];
    const float* b2a = (const float*)d_in[9];
    const float* W2b = (const float*)d_in[10];
    const float* g2b = (const float*)d_in[11];
    const float* b2b = (const float*)d_in[12];
    const float* W3a = (const float*)d_in[13];
    const float* g3a = (const float*)d_in[14];
    const float* b3a = (const float*)d_in[15];
    const float* W3b = (const float*)d_in[16];
    const float* g3b = (const float*)d_in[17];
    const float* b3b = (const float*)d_in[18];
    const float* eps1 = (const float*)d_in[19];
    const float* eps2 = (const float*)d_in[20];

    float *P, *Q, *cat, *lvl, *h2, *t2, *h3, *t3;
    __nv_bfloat16 *Whi, *Wlo;
    cudaGetSymbolAddress((void**)&P,   g_P);
    cudaGetSymbolAddress((void**)&Q,   g_Q);
    cudaGetSymbolAddress((void**)&cat, g_cat);
    cudaGetSymbolAddress((void**)&lvl, g_lvl);
    cudaGetSymbolAddress((void**)&h2,  g_h2);
    cudaGetSymbolAddress((void**)&t2,  g_t2);
    cudaGetSymbolAddress((void**)&h3,  g_h3);
    cudaGetSymbolAddress((void**)&t3,  g_t3);
    cudaGetSymbolAddress((void**)&Whi, g_Whi);
    cudaGetSymbolAddress((void**)&Wlo, g_Wlo);

    cudaFuncSetAttribute(gemm_mma<0, false>, cudaFuncAttributeMaxDynamicSharedMemorySize, SMEM_BYTES);
    cudaFuncSetAttribute(gemm_mma<1, true>,  cudaFuncAttributeMaxDynamicSharedMemorySize, SMEM_BYTES);
    cudaFuncSetAttribute(gemm_mma<2, true>,  cudaFuncAttributeMaxDynamicSharedMemorySize, SMEM_BYTES);

    float* node_out = (float*)d_out;
    float* edge_out = (float*)d_out + (size_t)NN * H;

    const int TN = (NN + 63) / 64;               // 1563 tiles
    const int TE = (NE + 63) / 64;               // 6250 tiles
    const int GN = (TN + TPC - 1) / TPC;         // 391 blocks
    const int GE = (TE + TPC - 1) / TPC;         // 1563 blocks

    zero_k<<<112500, 256>>>();
    wconv_k<<<48, 256>>>(W1, W2a, W2b, W3a, W3b);

    // P = node_rep @ W1[:128], Q = edge_rep @ W1[128:]
    gemm_mma<0, false><<<GN, 256, SMEM_BYTES>>>(node_rep, nullptr, 0, nullptr,
                                                Whi + 0 * H * H, Wlo + 0 * H * H, P, NN, 0, 0);
    gemm_mma<0, false><<<GE, 256, SMEM_BYTES>>>(edge_rep, nullptr, 0, nullptr,
                                                Whi + 1 * H * H, Wlo + 1 * H * H, Q, NE, 0, 0);

    stats_msg_k<<<1184, 256>>>(node_idx, edge_idx);
    finalize_k<<<1, 128>>>(0, g1, b1, 1.0f / NI);

    cat_k<<<NI / 8, 256>>>(node_rep, node_idx, edge_idx);
    lvl2_k<<<NI / 8, 256>>>(node_idx, edge_idx);

    // node path
    gemm_mma<1, true><<<GN, 256, SMEM_BYTES>>>(node_rep, lvl, H, eps1,
                                               Whi + 2 * H * H, Wlo + 2 * H * H, h2, NN, 0, 1);
    finalize_k<<<1, 128>>>(1, g2a, b2a, 1.0f / NN);
    gemm_mma<2, true><<<GN, 256, SMEM_BYTES>>>(h2, nullptr, 0, nullptr,
                                               Whi + 3 * H * H, Wlo + 3 * H * H, t2, NN, 1, 2);
    finalize_k<<<1, 128>>>(2, g2b, b2b, 1.0f / NN);
    bnout_k<<<(NN * H / 4 + 255) / 256, 256>>>(t2, 2, node_out, NN * H / 4);

    // edge path
    gemm_mma<1, true><<<GE, 256, SMEM_BYTES>>>(edge_rep, cat + H, 2 * H, eps2,
                                               Whi + 4 * H * H, Wlo + 4 * H * H, h3, NE, 0, 3);
    finalize_k<<<1, 128>>>(3, g3a, b3a, 1.0f / NE);
    gemm_mma<2, true><<<GE, 256, SMEM_BYTES>>>(h3, nullptr, 0, nullptr,
                                               Whi + 5 * H * H, Wlo + 5 * H * H, t3, NE, 3, 4);
    finalize_k<<<1, 128>>>(4, g3b, b3b, 1.0f / NE);
    bnout_k<<<(NE * H / 4 + 255) / 256, 256>>>(t3, 4, edge_out, NE * H / 4);
}

// round 13
// speedup vs baseline: 1.7010x; 1.0549x over previous
#include <cuda_runtime.h>
#include <cuda_bf16.h>
#include <cstdint>

#define H 128
#define NN 100000
#define NE 400000
#define NI 800000
#define BN_EPS 1e-5f
#define TPC 4   // GEMM M-tiles per CTA

// ---------------- scratch ----------------
__device__ float g_P[NN * H];
__device__ float g_Q[NE * H];
__device__ float g_cat[NE * 2 * H];
__device__ float g_lvl[NN * H];
__device__ float g_h2[NN * H];
__device__ float g_t2[NN * H];
__device__ float g_h3[NE * H];
__device__ float g_t3[NE * H];
__device__ double g_sum[5][H];
__device__ double g_sq[5][H];
__device__ float g_scale[5][H];
__device__ float g_shift[5][H];
// Preconverted weights: [n][k] bf16, 16B-granule XOR swizzle pre-applied.
__device__ __nv_bfloat16 g_Whi[6][H * H];
__device__ __nv_bfloat16 g_Wlo[6][H * H];

// ---------------- helpers ----------------
__device__ __forceinline__ uint32_t smem_u32(const void* p) {
    uint32_t a;
    asm("{ .reg .u64 t; cvta.to.shared.u64 t, %1; cvt.u32.u64 %0, t; }" : "=r"(a) : "l"(p));
    return a;
}
__device__ __forceinline__ void ldsm_x4(uint32_t r[4], uint32_t a) {
    asm volatile("ldmatrix.sync.aligned.m8n8.x4.shared.b16 {%0,%1,%2,%3}, [%4];"
                 : "=r"(r[0]), "=r"(r[1]), "=r"(r[2]), "=r"(r[3]) : "r"(a));
}
__device__ __forceinline__ void mma16816(float c[4], const uint32_t a[4], const uint32_t b[2]) {
    asm volatile("mma.sync.aligned.m16n8k16.row.col.f32.bf16.bf16.f32 "
                 "{%0,%1,%2,%3}, {%4,%5,%6,%7}, {%8,%9}, {%0,%1,%2,%3};"
                 : "+f"(c[0]), "+f"(c[1]), "+f"(c[2]), "+f"(c[3])
                 : "r"(a[0]), "r"(a[1]), "r"(a[2]), "r"(a[3]), "r"(b[0]), "r"(b[1]));
}
__device__ __forceinline__ void red4(float* p, float4 v) {
    asm volatile("red.global.add.v4.f32 [%0], {%1,%2,%3,%4};"
                 :: "l"(p), "f"(v.x), "f"(v.y), "f"(v.z), "f"(v.w) : "memory");
}
__device__ __forceinline__ float relu_aff(float x, float sc, float sh) {
    return fmaxf(fmaf(x, sc, sh), 0.f);
}

// ---------------- preconvert weights: W[k][n] -> hi/lo bf16 [n][k], pre-swizzled ----------------
__global__ void __launch_bounds__(256)
wconv_k(const float* __restrict__ W1, const float* __restrict__ W2a,
        const float* __restrict__ W2b, const float* __restrict__ W3a,
        const float* __restrict__ W3b)
{
    int m = blockIdx.x >> 3;
    int slice = blockIdx.x & 7;
    const float* src;
    switch (m) {
        case 0: src = W1; break;
        case 1: src = W1 + H * H; break;
        case 2: src = W2a; break;
        case 3: src = W2b; break;
        case 4: src = W3a; break;
        default: src = W3b; break;
    }
    int base = slice * 2048;
    for (int t = threadIdx.x; t < 2048; t += 256) {
        int idx = base + t;
        int n = idx >> 7, k = idx & 127;
        float v = src[k * H + n];
        uint32_t uv = __float_as_uint(v);
        uint32_t hb = uv & 0xFFFF0000u;
        float res = v - __uint_as_float(hb);
        uint32_t off = (uint32_t)n * 128u + ((((uint32_t)k >> 3) ^ ((uint32_t)n & 7)) << 3)
                     + ((uint32_t)k & 7);
        g_Whi[m][off] = __ushort_as_bfloat16((unsigned short)(hb >> 16));
        g_Wlo[m][off] = __float2bfloat16(res);
    }
}

// ---------------- mma.sync GEMM: C[M,128] = A[M,128] @ W, 3-way bf16 split ----------------
#define SMW_HI 0
#define SMW_LO 32768
#define SMA_HI 65536
#define SMA_LO 81920
#define SM_RED 98304
#define SMEM_BYTES (98304 + 1024)

template <int AMODE, bool STATS>
__global__ void __launch_bounds__(256)
gemm_mma(const float* __restrict__ A1, const float* __restrict__ A2, int lda2,
         const float* __restrict__ epsp,
         const __nv_bfloat16* __restrict__ Whi, const __nv_bfloat16* __restrict__ Wlo,
         float* __restrict__ C, int M, int inSet, int statSet)
{
    extern __shared__ char smem[];
    uint32_t sb = smem_u32(smem);
    const int tid = threadIdx.x;
    const int lane = tid & 31;
    const int wid = tid >> 5;

    // W images (32KB hi + 32KB lo), once per CTA
    {
        const uint4* shi = (const uint4*)Whi;
        const uint4* slo = (const uint4*)Wlo;
        uint4* dhi = (uint4*)(smem + SMW_HI);
        uint4* dlo = (uint4*)(smem + SMW_LO);
#pragma unroll
        for (int i = 0; i < 8; i++) {
            dhi[tid + i * 256] = shi[tid + i * 256];
            dlo[tid + i * 256] = slo[tid + i * 256];
        }
    }
    if (STATS) ((float*)(smem + SM_RED))[tid] = 0.f;  // sum[128] | sq[128]

    float alpha = 0.f;
    if (AMODE == 1) alpha = 1.0f + __ldg(epsp);

    const int wm = wid & 1;        // row group (32 rows)
    const int wn = wid >> 1;       // col group (32 cols)
    const int rb = wm * 32;
    const int cbc = wn * 32;
    const int gq = lane >> 2, rq = lane & 3;

    for (int t = 0; t < TPC; t++) {
        const int row0 = (blockIdx.x * TPC + t) * 64;
        if (row0 >= M) break;
        __syncthreads();   // previous tile's readers done before overwriting A

        // load A rows (64 x 128), transform, split hi/lo, store swizzled
        {
            const int r = tid >> 2;
            const int cq = tid & 3;
            const int arow = row0 + r;
            const bool valid = arow < M;
            const float* a1p = A1 + (size_t)arow * H + cq * 32;
            const float* a2p = (AMODE == 1) ? (A2 + (size_t)arow * lda2 + cq * 32) : nullptr;
#pragma unroll
            for (int g = 0; g < 4; g++) {
                float f[8];
                if (valid) {
                    float4 u0 = *(const float4*)(a1p + g * 8);
                    float4 u1 = *(const float4*)(a1p + g * 8 + 4);
                    f[0] = u0.x; f[1] = u0.y; f[2] = u0.z; f[3] = u0.w;
                    f[4] = u1.x; f[5] = u1.y; f[6] = u1.z; f[7] = u1.w;
                    if (AMODE == 1) {
                        float4 w0 = *(const float4*)(a2p + g * 8);
                        float4 w1 = *(const float4*)(a2p + g * 8 + 4);
                        f[0] = fmaf(alpha, f[0], w0.x); f[1] = fmaf(alpha, f[1], w0.y);
                        f[2] = fmaf(alpha, f[2], w0.z); f[3] = fmaf(alpha, f[3], w0.w);
                        f[4] = fmaf(alpha, f[4], w1.x); f[5] = fmaf(alpha, f[5], w1.y);
                        f[6] = fmaf(alpha, f[6], w1.z); f[7] = fmaf(alpha, f[7], w1.w);
                    } else if (AMODE == 2) {
                        int c0 = cq * 32 + g * 8;
#pragma unroll
                        for (int j = 0; j < 8; j++)
                            f[j] = relu_aff(f[j], g_scale[inSet][c0 + j], g_shift[inSet][c0 + j]);
                    }
                } else {
#pragma unroll
                    for (int j = 0; j < 8; j++) f[j] = 0.f;
                }
                uint32_t hv[4], lv[4];
#pragma unroll
                for (int j = 0; j < 4; j++) {
                    float a = f[2 * j], b = f[2 * j + 1];
                    uint32_t ua = __float_as_uint(a), ub = __float_as_uint(b);
                    hv[j] = __byte_perm(ua, ub, 0x7632);
                    float ra = a - __uint_as_float(ua & 0xFFFF0000u);
                    float rb2 = b - __uint_as_float(ub & 0xFFFF0000u);
                    __nv_bfloat162 lo2 = __floats2bfloat162_rn(ra, rb2);
                    lv[j] = *(uint32_t*)&lo2;
                }
                uint32_t gran = (uint32_t)((cq * 4 + g) ^ (r & 7));
                uint32_t off = (uint32_t)r * 256u + gran * 16u;
                *(uint4*)(smem + SMA_HI + off) = make_uint4(hv[0], hv[1], hv[2], hv[3]);
                *(uint4*)(smem + SMA_LO + off) = make_uint4(lv[0], lv[1], lv[2], lv[3]);
            }
        }
        __syncthreads();

        float acc[2][4][4];
#pragma unroll
        for (int mt = 0; mt < 2; mt++)
#pragma unroll
            for (int j = 0; j < 4; j++)
#pragma unroll
                for (int q = 0; q < 4; q++) acc[mt][j][q] = 0.f;

#pragma unroll
        for (int ks = 0; ks < 8; ks++) {
            const uint32_t kg = (uint32_t)ks * 2u;
            uint32_t ahi[2][4], alo[2][4];
#pragma unroll
            for (int mt = 0; mt < 2; mt++) {
                uint32_t rowA = (uint32_t)(rb + mt * 16 + (lane & 15));
                uint32_t gran = (kg + (uint32_t)(lane >> 4)) ^ (rowA & 7u);
                uint32_t a = sb + SMA_HI + rowA * 256u + gran * 16u;
                ldsm_x4(ahi[mt], a);
                ldsm_x4(alo[mt], a + 16384u);
            }
#pragma unroll
            for (int pr = 0; pr < 2; pr++) {
                uint32_t rowB = (uint32_t)(cbc + pr * 16 + ((lane >> 4) << 3) + (lane & 7));
                uint32_t kgr = kg + (uint32_t)((lane >> 3) & 1);
                uint32_t b = sb + SMW_HI + rowB * 256u + ((kgr ^ (rowB & 7u)) * 16u);
                uint32_t bh[4], bl[4];
                ldsm_x4(bh, b);
                ldsm_x4(bl, b + 32768u);
#pragma unroll
                for (int mt = 0; mt < 2; mt++) {
                    mma16816(acc[mt][pr * 2],     ahi[mt], bh);
                    mma16816(acc[mt][pr * 2],     ahi[mt], bl);
                    mma16816(acc[mt][pr * 2],     alo[mt], bh);
                    mma16816(acc[mt][pr * 2 + 1], ahi[mt], bh + 2);
                    mma16816(acc[mt][pr * 2 + 1], ahi[mt], bl + 2);
                    mma16816(acc[mt][pr * 2 + 1], alo[mt], bh + 2);
                }
            }
        }

        // epilogue: global stores
#pragma unroll
        for (int mt = 0; mt < 2; mt++) {
            int r0 = row0 + rb + mt * 16 + gq;
#pragma unroll
            for (int j = 0; j < 4; j++) {
                int col = cbc + j * 8 + rq * 2;
                if (r0 < M)
                    *(float2*)(C + (size_t)r0 * H + col) = make_float2(acc[mt][j][0], acc[mt][j][1]);
                if (r0 + 8 < M)
                    *(float2*)(C + (size_t)(r0 + 8) * H + col) = make_float2(acc[mt][j][2], acc[mt][j][3]);
            }
        }

        if (STATS) {
            float* s_sum = (float*)(smem + SM_RED);
            float* s_sq  = s_sum + 128;
#pragma unroll
            for (int j = 0; j < 4; j++) {
                float se = 0.f, so = 0.f, qe = 0.f, qo = 0.f;
#pragma unroll
                for (int mt = 0; mt < 2; mt++) {
                    float c0 = acc[mt][j][0], c1 = acc[mt][j][1];
                    float c2 = acc[mt][j][2], c3 = acc[mt][j][3];
                    se += c0 + c2; so += c1 + c3;
                    qe = fmaf(c0, c0, qe); qe = fmaf(c2, c2, qe);
                    qo = fmaf(c1, c1, qo); qo = fmaf(c3, c3, qo);
                }
#pragma unroll
                for (int o = 16; o >= 4; o >>= 1) {
                    se += __shfl_down_sync(0xFFFFFFFFu, se, o);
                    so += __shfl_down_sync(0xFFFFFFFFu, so, o);
                    qe += __shfl_down_sync(0xFFFFFFFFu, qe, o);
                    qo += __shfl_down_sync(0xFFFFFFFFu, qo, o);
                }
                if (lane < 4) {
                    int col = cbc + j * 8 + lane * 2;
                    atomicAdd(&s_sum[col],     se);
                    atomicAdd(&s_sum[col + 1], so);
                    atomicAdd(&s_sq[col],      qe);
                    atomicAdd(&s_sq[col + 1],  qo);
                }
            }
        }
    }

    if (STATS) {
        __syncthreads();
        float* s_sum = (float*)(smem + SM_RED);
        if (tid < 128)      atomicAdd(&g_sum[statSet][tid],       (double)s_sum[tid]);
        else                atomicAdd(&g_sq[statSet][tid - 128],  (double)s_sum[tid]);
    }
}

// ---------------- stats over msg_raw[i] = P[n_i] + Q[e_i] ----------------
__global__ void __launch_bounds__(256)
stats_msg_k(const int* __restrict__ node_idx, const int* __restrict__ edge_idx)
{
    const int lane = threadIdx.x & 31;
    const int w = threadIdx.x >> 5;
    const int c4 = lane << 2;
    float4 s = make_float4(0.f, 0.f, 0.f, 0.f);
    float4 q = make_float4(0.f, 0.f, 0.f, 0.f);
    for (int i = blockIdx.x * 8 + w; i < NI; i += gridDim.x * 8) {
        int n = node_idx[i], e = edge_idx[i];
        float4 p  = *(const float4*)(g_P + (size_t)n * H + c4);
        float4 qq = *(const float4*)(g_Q + (size_t)e * H + c4);
        float vx = p.x + qq.x, vy = p.y + qq.y, vz = p.z + qq.z, vw = p.w + qq.w;
        s.x += vx; s.y += vy; s.z += vz; s.w += vw;
        q.x = fmaf(vx, vx, q.x); q.y = fmaf(vy, vy, q.y);
        q.z = fmaf(vz, vz, q.z); q.w = fmaf(vw, vw, q.w);
    }
    __shared__ float red[8][128];
    red[w][c4 + 0] = s.x; red[w][c4 + 1] = s.y; red[w][c4 + 2] = s.z; red[w][c4 + 3] = s.w;
    __syncthreads();
    if (threadIdx.x < 128) {
        float t = 0.f;
#pragma unroll
        for (int r = 0; r < 8; r++) t += red[r][threadIdx.x];
        atomicAdd(&g_sum[0][threadIdx.x], (double)t);
    }
    __syncthreads();
    red[w][c4 + 0] = q.x; red[w][c4 + 1] = q.y; red[w][c4 + 2] = q.z; red[w][c4 + 3] = q.w;
    __syncthreads();
    if (threadIdx.x < 128) {
        float t = 0.f;
#pragma unroll
        for (int r = 0; r < 8; r++) t += red[r][threadIdx.x];
        atomicAdd(&g_sq[0][threadIdx.x], (double)t);
    }
}

// ---------------- finalize BN stats ----------------
__global__ void finalize_k(int set, const float* __restrict__ g,
                           const float* __restrict__ b, float invN)
{
    int j = threadIdx.x;
    double mean = g_sum[set][j] * (double)invN;
    double var = g_sq[set][j] * (double)invN - mean * mean;
    float sc = g[j] * rsqrtf((float)var + BN_EPS);
    g_scale[set][j] = sc;
    g_shift[set][j] = fmaf(-(float)mean, sc, b[j]);
}

// ---------------- cat pass: scatter msg/node_rep by edge, and -msg by node ----------------
__global__ void __launch_bounds__(256)
cat_k(const float* __restrict__ node_rep,
      const int* __restrict__ node_idx, const int* __restrict__ edge_idx)
{
    const int lane = threadIdx.x & 31;
    const int w = threadIdx.x >> 5;
    const int c4 = lane << 2;
    int i = blockIdx.x * 8 + w;
    if (i >= NI) return;
    int n = node_idx[i], e = edge_idx[i];
    float4 p = *(const float4*)(g_P + (size_t)n * H + c4);
    float4 q = *(const float4*)(g_Q + (size_t)e * H + c4);
    float4 sc = *(const float4*)&g_scale[0][c4];
    float4 sh = *(const float4*)&g_shift[0][c4];
    float4 m;
    m.x = relu_aff(p.x + q.x, sc.x, sh.x);
    m.y = relu_aff(p.y + q.y, sc.y, sh.y);
    m.z = relu_aff(p.z + q.z, sc.z, sh.z);
    m.w = relu_aff(p.w + q.w, sc.w, sh.w);
    red4(g_cat + (size_t)e * (2 * H) + c4, m);
    // lvl[n] -= msg_i  (other half added by lvl2_k after cat completes)
    red4(g_lvl + (size_t)n * H + c4, make_float4(-m.x, -m.y, -m.z, -m.w));
    float4 nr = *(const float4*)(node_rep + (size_t)n * H + c4);
    red4(g_cat + (size_t)e * (2 * H) + H + c4, nr);
}

// ---------------- lvl pass 2: lvl[n] += catm[e_i] (no P/Q re-gather) ----------------
__global__ void __launch_bounds__(256)
lvl2_k(const int* __restrict__ node_idx, const int* __restrict__ edge_idx)
{
    const int lane = threadIdx.x & 31;
    const int w = threadIdx.x >> 5;
    const int c4 = lane << 2;
    int i = blockIdx.x * 8 + w;
    if (i >= NI) return;
    int n = node_idx[i], e = edge_idx[i];
    float4 cv = *(const float4*)(g_cat + (size_t)e * (2 * H) + c4);
    red4(g_lvl + (size_t)n * H + c4, cv);
}

// ---------------- final elementwise bn_relu ----------------
__global__ void __launch_bounds__(256)
bnout_k(const float* __restrict__ in, int set, float* __restrict__ out, int n4)
{
    int t = blockIdx.x * blockDim.x + threadIdx.x;
    if (t >= n4) return;
    int c4 = (t & 31) << 2;
    float4 v = ((const float4*)in)[t];
    float4 sc = *(const float4*)&g_scale[set][c4];
    float4 sh = *(const float4*)&g_shift[set][c4];
    float4 o;
    o.x = relu_aff(v.x, sc.x, sh.x);
    o.y = relu_aff(v.y, sc.y, sh.y);
    o.z = relu_aff(v.z, sc.z, sh.z);
    o.w = relu_aff(v.w, sc.w, sh.w);
    ((float4*)out)[t] = o;
}

// ---------------- launch: forked-stream graph ----------------
extern "C" void kernel_launch(void* const* d_in, const int* in_sizes, int n_in,
                              void* d_out, int out_size)
{
    const float* node_rep = (const float*)d_in[0];
    const float* edge_rep = (const float*)d_in[1];
    const int*   node_idx = (const int*)d_in[2];
    const int*   edge_idx = (const int*)d_in[3];
    const float* W1  = (const float*)d_in[4];
    const float* g1  = (const float*)d_in[5];
    const float* b1  = (const float*)d_in[6];
    const float* W2a = (const float*)d_in[7];
    const float* g2a = (const float*)d_in[8];
    const float* b2a = (const float*)d_in[9];
    const float* W2b = (const float*)d_in[10];
    const float* g2b = (const float*)d_in[11];
    const float* b2b = (const float*)d_in[12];
    const float* W3a = (const float*)d_in[13];
    const float* g3a = (const float*)d_in[14];
    const float* b3a = (const float*)d_in[15];
    const float* W3b = (const float*)d_in[16];
    const float* g3b = (const float*)d_in[17];
    const float* b3b = (const float*)d_in[18];
    const float* eps1 = (const float*)d_in[19];
    const float* eps2 = (const float*)d_in[20];

    float *P, *Q, *cat, *lvl, *h2, *t2, *h3, *t3;
    double *sumP, *sqP;
    __nv_bfloat16 *Whi, *Wlo;
    cudaGetSymbolAddress((void**)&P,    g_P);
    cudaGetSymbolAddress((void**)&Q,    g_Q);
    cudaGetSymbolAddress((void**)&cat,  g_cat);
    cudaGetSymbolAddress((void**)&lvl,  g_lvl);
    cudaGetSymbolAddress((void**)&h2,   g_h2);
    cudaGetSymbolAddress((void**)&t2,   g_t2);
    cudaGetSymbolAddress((void**)&h3,   g_h3);
    cudaGetSymbolAddress((void**)&t3,   g_t3);
    cudaGetSymbolAddress((void**)&sumP, g_sum);
    cudaGetSymbolAddress((void**)&sqP,  g_sq);
    cudaGetSymbolAddress((void**)&Whi,  g_Whi);
    cudaGetSymbolAddress((void**)&Wlo,  g_Wlo);

    cudaFuncSetAttribute(gemm_mma<0, false>, cudaFuncAttributeMaxDynamicSharedMemorySize, SMEM_BYTES);
    cudaFuncSetAttribute(gemm_mma<1, true>,  cudaFuncAttributeMaxDynamicSharedMemorySize, SMEM_BYTES);
    cudaFuncSetAttribute(gemm_mma<2, true>,  cudaFuncAttributeMaxDynamicSharedMemorySize, SMEM_BYTES);

    float* node_out = (float*)d_out;
    float* edge_out = (float*)d_out + (size_t)NN * H;

    const int TN = (NN + 63) / 64;
    const int TE = (NE + 63) / 64;
    const int GN = (TN + TPC - 1) / TPC;
    const int GE = (TE + TPC - 1) / TPC;

    cudaStream_t sA, sB;
    cudaStreamCreateWithFlags(&sA, cudaStreamNonBlocking);
    cudaStreamCreateWithFlags(&sB, cudaStreamNonBlocking);
    cudaEvent_t eFork, eW, eP, eZero, eCat, eEdge;
    cudaEventCreateWithFlags(&eFork, cudaEventDisableTiming);
    cudaEventCreateWithFlags(&eW,    cudaEventDisableTiming);
    cudaEventCreateWithFlags(&eP,    cudaEventDisableTiming);
    cudaEventCreateWithFlags(&eZero, cudaEventDisableTiming);
    cudaEventCreateWithFlags(&eCat,  cudaEventDisableTiming);
    cudaEventCreateWithFlags(&eEdge, cudaEventDisableTiming);

    // fork sA, sB off the capture-origin (default) stream
    cudaEventRecord(eFork, 0);
    cudaStreamWaitEvent(sA, eFork, 0);
    cudaStreamWaitEvent(sB, eFork, 0);

    // sB: zero accumulators (memset nodes, overlap with wconv + P/Q gemms)
    cudaMemsetAsync(cat,  0, (size_t)NE * 2 * H * sizeof(float), sB);
    cudaMemsetAsync(lvl,  0, (size_t)NN * H * sizeof(float), sB);
    cudaMemsetAsync(sumP, 0, 5 * H * sizeof(double), sB);
    cudaMemsetAsync(sqP,  0, 5 * H * sizeof(double), sB);
    cudaEventRecord(eZero, sB);

    // s0: weight conversion
    wconv_k<<<48, 256>>>(W1, W2a, W2b, W3a, W3b);
    cudaEventRecord(eW, 0);

    // sA: P = node_rep @ W1[:128]   (parallel with Q-gemm on s0)
    cudaStreamWaitEvent(sA, eW, 0);
    gemm_mma<0, false><<<GN, 256, SMEM_BYTES, sA>>>(node_rep, nullptr, 0, nullptr,
                                                    Whi + 0 * H * H, Wlo + 0 * H * H, P, NN, 0, 0);
    cudaEventRecord(eP, sA);

    // s0: Q = edge_rep @ W1[128:]
    gemm_mma<0, false><<<GE, 256, SMEM_BYTES>>>(edge_rep, nullptr, 0, nullptr,
                                                Whi + 1 * H * H, Wlo + 1 * H * H, Q, NE, 0, 0);

    // s0: BN1 stats + cat scatter (needs P, Q, zeroed accumulators)
    cudaStreamWaitEvent(0, eP, 0);
    cudaStreamWaitEvent(0, eZero, 0);
    stats_msg_k<<<1184, 256>>>(node_idx, edge_idx);
    finalize_k<<<1, 128>>>(0, g1, b1, 1.0f / NI);
    cat_k<<<NI / 8, 256>>>(node_rep, node_idx, edge_idx);
    cudaEventRecord(eCat, 0);

    // sA: edge path (needs only cat[:,H:] -> runs parallel with lvl2 + node path)
    cudaStreamWaitEvent(sA, eCat, 0);
    gemm_mma<1, true><<<GE, 256, SMEM_BYTES, sA>>>(edge_rep, cat + H, 2 * H, eps2,
                                                   Whi + 4 * H * H, Wlo + 4 * H * H, h3, NE, 0, 3);
    finalize_k<<<1, 128, 0, sA>>>(3, g3a, b3a, 1.0f / NE);
    gemm_mma<2, true><<<GE, 256, SMEM_BYTES, sA>>>(h3, nullptr, 0, nullptr,
                                                   Whi + 5 * H * H, Wlo + 5 * H * H, t3, NE, 3, 4);
    finalize_k<<<1, 128, 0, sA>>>(4, g3b, b3b, 1.0f / NE);
    bnout_k<<<(NE * H / 4 + 255) / 256, 256, 0, sA>>>(t3, 4, edge_out, NE * H / 4);
    cudaEventRecord(eEdge, sA);

    // s0: lvl completion + node path
    lvl2_k<<<NI / 8, 256>>>(node_idx, edge_idx);
    gemm_mma<1, true><<<GN, 256, SMEM_BYTES>>>(node_rep, lvl, H, eps1,
                                               Whi + 2 * H * H, Wlo + 2 * H * H, h2, NN, 0, 1);
    finalize_k<<<1, 128>>>(1, g2a, b2a, 1.0f / NN);
    gemm_mma<2, true><<<GN, 256, SMEM_BYTES>>>(h2, nullptr, 0, nullptr,
                                               Whi + 3 * H * H, Wlo + 3 * H * H, t2, NN, 1, 2);
    finalize_k<<<1, 128>>>(2, g2b, b2b, 1.0f / NN);
    bnout_k<<<(NN * H / 4 + 255) / 256, 256>>>(t2, 2, node_out, NN * H / 4);

    // join edge branch back into origin stream
    cudaStreamWaitEvent(0, eEdge, 0);

    cudaEventDestroy(eFork);
    cudaEventDestroy(eW);
    cudaEventDestroy(eP);
    cudaEventDestroy(eZero);
    cudaEventDestroy(eCat);
    cudaEventDestroy(eEdge);
    cudaStreamDestroy(sA);
    cudaStreamDestroy(sB);
}

// round 15
// speedup vs baseline: 1.7514x; 1.0297x over previous
#include <cuda_runtime.h>
#include <cuda_bf16.h>
#include <cstdint>

#define H 128
#define NN 100000
#define NE 400000
#define NI 800000
#define BN_EPS 1e-5f
#define TPC 4   // GEMM M-tiles per CTA

// ---------------- scratch ----------------
__device__ float g_P[NN * H];
__device__ float g_Q[NE * H];
__device__ float g_cat[NE * 2 * H];
__device__ float g_lvl[NN * H];
__device__ float g_h2[NN * H];
__device__ float g_t2[NN * H];
__device__ float g_h3[NE * H];
__device__ float g_t3[NE * H];
__device__ double g_sum[5][H];
__device__ double g_sq[5][H];
__device__ float g_scale[5][H];
__device__ float g_shift[5][H];
// Preconverted weights: [n][k] bf16, 16B-granule XOR swizzle pre-applied.
__device__ __nv_bfloat16 g_Whi[6][H * H];
__device__ __nv_bfloat16 g_Wlo[6][H * H];

// ---------------- helpers ----------------
__device__ __forceinline__ uint32_t smem_u32(const void* p) {
    uint32_t a;
    asm("{ .reg .u64 t; cvta.to.shared.u64 t, %1; cvt.u32.u64 %0, t; }" : "=r"(a) : "l"(p));
    return a;
}
__device__ __forceinline__ void ldsm_x4(uint32_t r[4], uint32_t a) {
    asm volatile("ldmatrix.sync.aligned.m8n8.x4.shared.b16 {%0,%1,%2,%3}, [%4];"
                 : "=r"(r[0]), "=r"(r[1]), "=r"(r[2]), "=r"(r[3]) : "r"(a));
}
__device__ __forceinline__ void mma16816(float c[4], const uint32_t a[4], const uint32_t b[2]) {
    asm volatile("mma.sync.aligned.m16n8k16.row.col.f32.bf16.bf16.f32 "
                 "{%0,%1,%2,%3}, {%4,%5,%6,%7}, {%8,%9}, {%0,%1,%2,%3};"
                 : "+f"(c[0]), "+f"(c[1]), "+f"(c[2]), "+f"(c[3])
                 : "r"(a[0]), "r"(a[1]), "r"(a[2]), "r"(a[3]), "r"(b[0]), "r"(b[1]));
}
__device__ __forceinline__ void red4(float* p, float4 v) {
    asm volatile("red.global.add.v4.f32 [%0], {%1,%2,%3,%4};"
                 :: "l"(p), "f"(v.x), "f"(v.y), "f"(v.z), "f"(v.w) : "memory");
}
__device__ __forceinline__ float relu_aff(float x, float sc, float sh) {
    return fmaxf(fmaf(x, sc, sh), 0.f);
}

// ---------------- preconvert weights: W[k][n] -> hi/lo bf16 [n][k], pre-swizzled ----------------
__global__ void __launch_bounds__(256)
wconv_k(const float* __restrict__ W1, const float* __restrict__ W2a,
        const float* __restrict__ W2b, const float* __restrict__ W3a,
        const float* __restrict__ W3b)
{
    int m = blockIdx.x >> 3;
    int slice = blockIdx.x & 7;
    const float* src;
    switch (m) {
        case 0: src = W1; break;
        case 1: src = W1 + H * H; break;
        case 2: src = W2a; break;
        case 3: src = W2b; break;
        case 4: src = W3a; break;
        default: src = W3b; break;
    }
    int base = slice * 2048;
    for (int t = threadIdx.x; t < 2048; t += 256) {
        int idx = base + t;
        int n = idx >> 7, k = idx & 127;
        float v = src[k * H + n];
        uint32_t uv = __float_as_uint(v);
        uint32_t hb = uv & 0xFFFF0000u;
        float res = v - __uint_as_float(hb);
        uint32_t off = (uint32_t)n * 128u + ((((uint32_t)k >> 3) ^ ((uint32_t)n & 7)) << 3)
                     + ((uint32_t)k & 7);
        g_Whi[m][off] = __ushort_as_bfloat16((unsigned short)(hb >> 16));
        g_Wlo[m][off] = __float2bfloat16(res);
    }
}

// ---------------- mma.sync GEMM: C[M,128] = A[M,128] @ W, 3-way bf16 split ----------------
#define SMW_HI 0
#define SMW_LO 32768
#define SMA_HI 65536
#define SMA_LO 81920
#define SM_RED 98304
#define SMEM_BYTES (98304 + 1024)

template <int AMODE, bool STATS>
__global__ void __launch_bounds__(256)
gemm_mma(const float* __restrict__ A1, const float* __restrict__ A2, int lda2,
         const float* __restrict__ epsp,
         const __nv_bfloat16* __restrict__ Whi, const __nv_bfloat16* __restrict__ Wlo,
         float* __restrict__ C, int M, int inSet, int statSet)
{
    extern __shared__ char smem[];
    uint32_t sb = smem_u32(smem);
    const int tid = threadIdx.x;
    const int lane = tid & 31;
    const int wid = tid >> 5;

    // W images (32KB hi + 32KB lo), once per CTA
    {
        const uint4* shi = (const uint4*)Whi;
        const uint4* slo = (const uint4*)Wlo;
        uint4* dhi = (uint4*)(smem + SMW_HI);
        uint4* dlo = (uint4*)(smem + SMW_LO);
#pragma unroll
        for (int i = 0; i < 8; i++) {
            dhi[tid + i * 256] = shi[tid + i * 256];
            dlo[tid + i * 256] = slo[tid + i * 256];
        }
    }
    if (STATS) ((float*)(smem + SM_RED))[tid] = 0.f;  // sum[128] | sq[128]

    float alpha = 0.f;
    if (AMODE == 1) alpha = 1.0f + __ldg(epsp);

    const int wm = wid & 1;        // row group (32 rows)
    const int wn = wid >> 1;       // col group (32 cols)
    const int rb = wm * 32;
    const int cbc = wn * 32;
    const int gq = lane >> 2, rq = lane & 3;

    for (int t = 0; t < TPC; t++) {
        const int row0 = (blockIdx.x * TPC + t) * 64;
        if (row0 >= M) break;
        __syncthreads();   // previous tile's readers done before overwriting A

        // load A rows (64 x 128), transform, split hi/lo, store swizzled
        {
            const int r = tid >> 2;
            const int cq = tid & 3;
            const int arow = row0 + r;
            const bool valid = arow < M;
            const float* a1p = A1 + (size_t)arow * H + cq * 32;
            const float* a2p = (AMODE == 1) ? (A2 + (size_t)arow * lda2 + cq * 32) : nullptr;
#pragma unroll
            for (int g = 0; g < 4; g++) {
                float f[8];
                if (valid) {
                    float4 u0 = *(const float4*)(a1p + g * 8);
                    float4 u1 = *(const float4*)(a1p + g * 8 + 4);
                    f[0] = u0.x; f[1] = u0.y; f[2] = u0.z; f[3] = u0.w;
                    f[4] = u1.x; f[5] = u1.y; f[6] = u1.z; f[7] = u1.w;
                    if (AMODE == 1) {
                        float4 w0 = *(const float4*)(a2p + g * 8);
                        float4 w1 = *(const float4*)(a2p + g * 8 + 4);
                        f[0] = fmaf(alpha, f[0], w0.x); f[1] = fmaf(alpha, f[1], w0.y);
                        f[2] = fmaf(alpha, f[2], w0.z); f[3] = fmaf(alpha, f[3], w0.w);
                        f[4] = fmaf(alpha, f[4], w1.x); f[5] = fmaf(alpha, f[5], w1.y);
                        f[6] = fmaf(alpha, f[6], w1.z); f[7] = fmaf(alpha, f[7], w1.w);
                    } else if (AMODE == 2) {
                        int c0 = cq * 32 + g * 8;
#pragma unroll
                        for (int j = 0; j < 8; j++)
                            f[j] = relu_aff(f[j], g_scale[inSet][c0 + j], g_shift[inSet][c0 + j]);
                    }
                } else {
#pragma unroll
                    for (int j = 0; j < 8; j++) f[j] = 0.f;
                }
                uint32_t hv[4], lv[4];
#pragma unroll
                for (int j = 0; j < 4; j++) {
                    float a = f[2 * j], b = f[2 * j + 1];
                    uint32_t ua = __float_as_uint(a), ub = __float_as_uint(b);
                    hv[j] = __byte_perm(ua, ub, 0x7632);
                    float ra = a - __uint_as_float(ua & 0xFFFF0000u);
                    float rb2 = b - __uint_as_float(ub & 0xFFFF0000u);
                    __nv_bfloat162 lo2 = __floats2bfloat162_rn(ra, rb2);
                    lv[j] = *(uint32_t*)&lo2;
                }
                uint32_t gran = (uint32_t)((cq * 4 + g) ^ (r & 7));
                uint32_t off = (uint32_t)r * 256u + gran * 16u;
                *(uint4*)(smem + SMA_HI + off) = make_uint4(hv[0], hv[1], hv[2], hv[3]);
                *(uint4*)(smem + SMA_LO + off) = make_uint4(lv[0], lv[1], lv[2], lv[3]);
            }
        }
        __syncthreads();

        float acc[2][4][4];
#pragma unroll
        for (int mt = 0; mt < 2; mt++)
#pragma unroll
            for (int j = 0; j < 4; j++)
#pragma unroll
                for (int q = 0; q < 4; q++) acc[mt][j][q] = 0.f;

#pragma unroll
        for (int ks = 0; ks < 8; ks++) {
            const uint32_t kg = (uint32_t)ks * 2u;
            uint32_t ahi[2][4], alo[2][4];
#pragma unroll
            for (int mt = 0; mt < 2; mt++) {
                uint32_t rowA = (uint32_t)(rb + mt * 16 + (lane & 15));
                uint32_t gran = (kg + (uint32_t)(lane >> 4)) ^ (rowA & 7u);
                uint32_t a = sb + SMA_HI + rowA * 256u + gran * 16u;
                ldsm_x4(ahi[mt], a);
                ldsm_x4(alo[mt], a + 16384u);
            }
#pragma unroll
            for (int pr = 0; pr < 2; pr++) {
                uint32_t rowB = (uint32_t)(cbc + pr * 16 + ((lane >> 4) << 3) + (lane & 7));
                uint32_t kgr = kg + (uint32_t)((lane >> 3) & 1);
                uint32_t b = sb + SMW_HI + rowB * 256u + ((kgr ^ (rowB & 7u)) * 16u);
                uint32_t bh[4], bl[4];
                ldsm_x4(bh, b);
                ldsm_x4(bl, b + 32768u);
#pragma unroll
                for (int mt = 0; mt < 2; mt++) {
                    mma16816(acc[mt][pr * 2],     ahi[mt], bh);
                    mma16816(acc[mt][pr * 2],     ahi[mt], bl);
                    mma16816(acc[mt][pr * 2],     alo[mt], bh);
                    mma16816(acc[mt][pr * 2 + 1], ahi[mt], bh + 2);
                    mma16816(acc[mt][pr * 2 + 1], ahi[mt], bl + 2);
                    mma16816(acc[mt][pr * 2 + 1], alo[mt], bh + 2);
                }
            }
        }

        // epilogue: global stores
#pragma unroll
        for (int mt = 0; mt < 2; mt++) {
            int r0 = row0 + rb + mt * 16 + gq;
#pragma unroll
            for (int j = 0; j < 4; j++) {
                int col = cbc + j * 8 + rq * 2;
                if (r0 < M)
                    *(float2*)(C + (size_t)r0 * H + col) = make_float2(acc[mt][j][0], acc[mt][j][1]);
                if (r0 + 8 < M)
                    *(float2*)(C + (size_t)(r0 + 8) * H + col) = make_float2(acc[mt][j][2], acc[mt][j][3]);
            }
        }

        if (STATS) {
            float* s_sum = (float*)(smem + SM_RED);
            float* s_sq  = s_sum + 128;
#pragma unroll
            for (int j = 0; j < 4; j++) {
                float se = 0.f, so = 0.f, qe = 0.f, qo = 0.f;
#pragma unroll
                for (int mt = 0; mt < 2; mt++) {
                    float c0 = acc[mt][j][0], c1 = acc[mt][j][1];
                    float c2 = acc[mt][j][2], c3 = acc[mt][j][3];
                    se += c0 + c2; so += c1 + c3;
                    qe = fmaf(c0, c0, qe); qe = fmaf(c2, c2, qe);
                    qo = fmaf(c1, c1, qo); qo = fmaf(c3, c3, qo);
                }
#pragma unroll
                for (int o = 16; o >= 4; o >>= 1) {
                    se += __shfl_down_sync(0xFFFFFFFFu, se, o);
                    so += __shfl_down_sync(0xFFFFFFFFu, so, o);
                    qe += __shfl_down_sync(0xFFFFFFFFu, qe, o);
                    qo += __shfl_down_sync(0xFFFFFFFFu, qo, o);
                }
                if (lane < 4) {
                    int col = cbc + j * 8 + lane * 2;
                    atomicAdd(&s_sum[col],     se);
                    atomicAdd(&s_sum[col + 1], so);
                    atomicAdd(&s_sq[col],      qe);
                    atomicAdd(&s_sq[col + 1],  qo);
                }
            }
        }
    }

    if (STATS) {
        __syncthreads();
        float* s_sum = (float*)(smem + SM_RED);
        if (tid < 128)      atomicAdd(&g_sum[statSet][tid],       (double)s_sum[tid]);
        else                atomicAdd(&g_sq[statSet][tid - 128],  (double)s_sum[tid]);
    }
}

// ---------------- stats over msg_raw[i] = P[n_i] + Q[e_i] ----------------
__global__ void __launch_bounds__(256)
stats_msg_k(const int* __restrict__ node_idx, const int* __restrict__ edge_idx)
{
    const int lane = threadIdx.x & 31;
    const int w = threadIdx.x >> 5;
    const int c4 = lane << 2;
    float4 s = make_float4(0.f, 0.f, 0.f, 0.f);
    float4 q = make_float4(0.f, 0.f, 0.f, 0.f);
    for (int i = blockIdx.x * 8 + w; i < NI; i += gridDim.x * 8) {
        int n = node_idx[i], e = edge_idx[i];
        float4 p  = *(const float4*)(g_P + (size_t)n * H + c4);
        float4 qq = *(const float4*)(g_Q + (size_t)e * H + c4);
        float vx = p.x + qq.x, vy = p.y + qq.y, vz = p.z + qq.z, vw = p.w + qq.w;
        s.x += vx; s.y += vy; s.z += vz; s.w += vw;
        q.x = fmaf(vx, vx, q.x); q.y = fmaf(vy, vy, q.y);
        q.z = fmaf(vz, vz, q.z); q.w = fmaf(vw, vw, q.w);
    }
    __shared__ float red[8][128];
    red[w][c4 + 0] = s.x; red[w][c4 + 1] = s.y; red[w][c4 + 2] = s.z; red[w][c4 + 3] = s.w;
    __syncthreads();
    if (threadIdx.x < 128) {
        float t = 0.f;
#pragma unroll
        for (int r = 0; r < 8; r++) t += red[r][threadIdx.x];
        atomicAdd(&g_sum[0][threadIdx.x], (double)t);
    }
    __syncthreads();
    red[w][c4 + 0] = q.x; red[w][c4 + 1] = q.y; red[w][c4 + 2] = q.z; red[w][c4 + 3] = q.w;
    __syncthreads();
    if (threadIdx.x < 128) {
        float t = 0.f;
#pragma unroll
        for (int r = 0; r < 8; r++) t += red[r][threadIdx.x];
        atomicAdd(&g_sq[0][threadIdx.x], (double)t);
    }
}

// ---------------- finalize BN stats ----------------
__global__ void finalize_k(int set, const float* __restrict__ g,
                           const float* __restrict__ b, float invN)
{
    int j = threadIdx.x;
    double mean = g_sum[set][j] * (double)invN;
    double var = g_sq[set][j] * (double)invN - mean * mean;
    float sc = g[j] * rsqrtf((float)var + BN_EPS);
    g_scale[set][j] = sc;
    g_shift[set][j] = fmaf(-(float)mean, sc, b[j]);
}

// ---------------- lift pass: cat[e, H:] += node_rep[n_i]  (independent of BN1) ----------------
__global__ void __launch_bounds__(256)
lift_k(const float* __restrict__ node_rep,
       const int* __restrict__ node_idx, const int* __restrict__ edge_idx)
{
    const int lane = threadIdx.x & 31;
    const int w = threadIdx.x >> 5;
    const int c4 = lane << 2;
    int i = blockIdx.x * 8 + w;
    if (i >= NI) return;
    int n = node_idx[i], e = edge_idx[i];
    float4 nr = *(const float4*)(node_rep + (size_t)n * H + c4);
    red4(g_cat + (size_t)e * (2 * H) + H + c4, nr);
}

// ---------------- catm pass: cat[e,:H] += msg, lvl[n] -= msg ----------------
__global__ void __launch_bounds__(256)
catm_k(const int* __restrict__ node_idx, const int* __restrict__ edge_idx)
{
    const int lane = threadIdx.x & 31;
    const int w = threadIdx.x >> 5;
    const int c4 = lane << 2;
    int i = blockIdx.x * 8 + w;
    if (i >= NI) return;
    int n = node_idx[i], e = edge_idx[i];
    float4 p = *(const float4*)(g_P + (size_t)n * H + c4);
    float4 q = *(const float4*)(g_Q + (size_t)e * H + c4);
    float4 sc = *(const float4*)&g_scale[0][c4];
    float4 sh = *(const float4*)&g_shift[0][c4];
    float4 m;
    m.x = relu_aff(p.x + q.x, sc.x, sh.x);
    m.y = relu_aff(p.y + q.y, sc.y, sh.y);
    m.z = relu_aff(p.z + q.z, sc.z, sh.z);
    m.w = relu_aff(p.w + q.w, sc.w, sh.w);
    red4(g_cat + (size_t)e * (2 * H) + c4, m);
    red4(g_lvl + (size_t)n * H + c4, make_float4(-m.x, -m.y, -m.z, -m.w));
}

// ---------------- lvl pass 2: lvl[n] += catm[e_i] ----------------
__global__ void __launch_bounds__(256)
lvl2_k(const int* __restrict__ node_idx, const int* __restrict__ edge_idx)
{
    const int lane = threadIdx.x & 31;
    const int w = threadIdx.x >> 5;
    const int c4 = lane << 2;
    int i = blockIdx.x * 8 + w;
    if (i >= NI) return;
    int n = node_idx[i], e = edge_idx[i];
    float4 cv = *(const float4*)(g_cat + (size_t)e * (2 * H) + c4);
    red4(g_lvl + (size_t)n * H + c4, cv);
}

// ---------------- final elementwise bn_relu ----------------
__global__ void __launch_bounds__(256)
bnout_k(const float* __restrict__ in, int set, float* __restrict__ out, int n4)
{
    int t = blockIdx.x * blockDim.x + threadIdx.x;
    if (t >= n4) return;
    int c4 = (t & 31) << 2;
    float4 v = ((const float4*)in)[t];
    float4 sc = *(const float4*)&g_scale[set][c4];
    float4 sh = *(const float4*)&g_shift[set][c4];
    float4 o;
    o.x = relu_aff(v.x, sc.x, sh.x);
    o.y = relu_aff(v.y, sc.y, sh.y);
    o.z = relu_aff(v.z, sc.z, sh.z);
    o.w = relu_aff(v.w, sc.w, sh.w);
    ((float4*)out)[t] = o;
}

// ---------------- launch: forked-stream graph ----------------
extern "C" void kernel_launch(void* const* d_in, const int* in_sizes, int n_in,
                              void* d_out, int out_size)
{
    const float* node_rep = (const float*)d_in[0];
    const float* edge_rep = (const float*)d_in[1];
    const int*   node_idx = (const int*)d_in[2];
    const int*   edge_idx = (const int*)d_in[3];
    const float* W1  = (const float*)d_in[4];
    const float* g1  = (const float*)d_in[5];
    const float* b1  = (const float*)d_in[6];
    const float* W2a = (const float*)d_in[7];
    const float* g2a = (const float*)d_in[8];
    const float* b2a = (const float*)d_in[9];
    const float* W2b = (const float*)d_in[10];
    const float* g2b = (const float*)d_in[11];
    const float* b2b = (const float*)d_in[12];
    const float* W3a = (const float*)d_in[13];
    const float* g3a = (const float*)d_in[14];
    const float* b3a = (const float*)d_in[15];
    const float* W3b = (const float*)d_in[16];
    const float* g3b = (const float*)d_in[17];
    const float* b3b = (const float*)d_in[18];
    const float* eps1 = (const float*)d_in[19];
    const float* eps2 = (const float*)d_in[20];

    float *P, *Q, *cat, *lvl, *h2, *t2, *h3, *t3;
    double *sumP, *sqP;
    __nv_bfloat16 *Whi, *Wlo;
    cudaGetSymbolAddress((void**)&P,    g_P);
    cudaGetSymbolAddress((void**)&Q,    g_Q);
    cudaGetSymbolAddress((void**)&cat,  g_cat);
    cudaGetSymbolAddress((void**)&lvl,  g_lvl);
    cudaGetSymbolAddress((void**)&h2,   g_h2);
    cudaGetSymbolAddress((void**)&t2,   g_t2);
    cudaGetSymbolAddress((void**)&h3,   g_h3);
    cudaGetSymbolAddress((void**)&t3,   g_t3);
    cudaGetSymbolAddress((void**)&sumP, g_sum);
    cudaGetSymbolAddress((void**)&sqP,  g_sq);
    cudaGetSymbolAddress((void**)&Whi,  g_Whi);
    cudaGetSymbolAddress((void**)&Wlo,  g_Wlo);

    cudaFuncSetAttribute(gemm_mma<0, false>, cudaFuncAttributeMaxDynamicSharedMemorySize, SMEM_BYTES);
    cudaFuncSetAttribute(gemm_mma<1, true>,  cudaFuncAttributeMaxDynamicSharedMemorySize, SMEM_BYTES);
    cudaFuncSetAttribute(gemm_mma<2, true>,  cudaFuncAttributeMaxDynamicSharedMemorySize, SMEM_BYTES);

    float* node_out = (float*)d_out;
    float* edge_out = (float*)d_out + (size_t)NN * H;

    const int TN = (NN + 63) / 64;
    const int TE = (NE + 63) / 64;
    const int GN = (TN + TPC - 1) / TPC;
    const int GE = (TE + TPC - 1) / TPC;

    cudaStream_t sA, sB;
    cudaStreamCreateWithFlags(&sA, cudaStreamNonBlocking);
    cudaStreamCreateWithFlags(&sB, cudaStreamNonBlocking);
    cudaEvent_t eFork, eW, eP, eZero, eEdge;
    cudaEventCreateWithFlags(&eFork, cudaEventDisableTiming);
    cudaEventCreateWithFlags(&eW,    cudaEventDisableTiming);
    cudaEventCreateWithFlags(&eP,    cudaEventDisableTiming);
    cudaEventCreateWithFlags(&eZero, cudaEventDisableTiming);
    cudaEventCreateWithFlags(&eEdge, cudaEventDisableTiming);

    // fork sA, sB off the capture-origin (default) stream
    cudaEventRecord(eFork, 0);
    cudaStreamWaitEvent(sA, eFork, 0);
    cudaStreamWaitEvent(sB, eFork, 0);

    // sB: zero accumulators, then lift scatter (independent of P/Q/BN1),
    //     then the ENTIRE edge path (needs only cat[:,H:] + W3a/W3b).
    cudaMemsetAsync(cat,  0, (size_t)NE * 2 * H * sizeof(float), sB);
    cudaMemsetAsync(lvl,  0, (size_t)NN * H * sizeof(float), sB);
    cudaMemsetAsync(sumP, 0, 5 * H * sizeof(double), sB);
    cudaMemsetAsync(sqP,  0, 5 * H * sizeof(double), sB);
    cudaEventRecord(eZero, sB);
    lift_k<<<NI / 8, 256, 0, sB>>>(node_rep, node_idx, edge_idx);

    // s0: weight conversion
    wconv_k<<<48, 256>>>(W1, W2a, W2b, W3a, W3b);
    cudaEventRecord(eW, 0);

    // sA: P = node_rep @ W1[:128]   (parallel with Q-gemm on s0)
    cudaStreamWaitEvent(sA, eW, 0);
    gemm_mma<0, false><<<GN, 256, SMEM_BYTES, sA>>>(node_rep, nullptr, 0, nullptr,
                                                    Whi + 0 * H * H, Wlo + 0 * H * H, P, NN, 0, 0);
    cudaEventRecord(eP, sA);

    // s0: Q = edge_rep @ W1[128:]
    gemm_mma<0, false><<<GE, 256, SMEM_BYTES>>>(edge_rep, nullptr, 0, nullptr,
                                                Whi + 1 * H * H, Wlo + 1 * H * H, Q, NE, 0, 0);

    // sB: edge path (lift done; W done; stats memset done on sB itself)
    cudaStreamWaitEvent(sB, eW, 0);
    gemm_mma<1, true><<<GE, 256, SMEM_BYTES, sB>>>(edge_rep, cat + H, 2 * H, eps2,
                                                   Whi + 4 * H * H, Wlo + 4 * H * H, h3, NE, 0, 3);
    finalize_k<<<1, 128, 0, sB>>>(3, g3a, b3a, 1.0f / NE);
    gemm_mma<2, true><<<GE, 256, SMEM_BYTES, sB>>>(h3, nullptr, 0, nullptr,
                                                   Whi + 5 * H * H, Wlo + 5 * H * H, t3, NE, 3, 4);
    finalize_k<<<1, 128, 0, sB>>>(4, g3b, b3b, 1.0f / NE);
    bnout_k<<<(NE * H / 4 + 255) / 256, 256, 0, sB>>>(t3, 4, edge_out, NE * H / 4);
    cudaEventRecord(eEdge, sB);

    // s0: BN1 stats + msg scatter + lvl + node path
    cudaStreamWaitEvent(0, eP, 0);
    cudaStreamWaitEvent(0, eZero, 0);
    stats_msg_k<<<1184, 256>>>(node_idx, edge_idx);
    finalize_k<<<1, 128>>>(0, g1, b1, 1.0f / NI);
    catm_k<<<NI / 8, 256>>>(node_idx, edge_idx);
    lvl2_k<<<NI / 8, 256>>>(node_idx, edge_idx);
    gemm_mma<1, true><<<GN, 256, SMEM_BYTES>>>(node_rep, lvl, H, eps1,
                                               Whi + 2 * H * H, Wlo + 2 * H * H, h2, NN, 0, 1);
    finalize_k<<<1, 128>>>(1, g2a, b2a, 1.0f / NN);
    gemm_mma<2, true><<<GN, 256, SMEM_BYTES>>>(h2, nullptr, 0, nullptr,
                                               Whi + 3 * H * H, Wlo + 3 * H * H, t2, NN, 1, 2);
    finalize_k<<<1, 128>>>(2, g2b, b2b, 1.0f / NN);
    bnout_k<<<(NN * H / 4 + 255) / 256, 256>>>(t2, 2, node_out, NN * H / 4);

    // join edge branch back into origin stream
    cudaStreamWaitEvent(0, eEdge, 0);

    cudaEventDestroy(eFork);
    cudaEventDestroy(eW);
    cudaEventDestroy(eP);
    cudaEventDestroy(eZero);
    cudaEventDestroy(eEdge);
    cudaStreamDestroy(sA);
    cudaStreamDestroy(sB);
}

// round 16
// speedup vs baseline: 1.8291x; 1.0443x over previous
#include <cuda_runtime.h>
#include <cuda_bf16.h>
#include <cstdint>

#define H 128
#define NN 100000
#define NE 400000
#define NI 800000
#define BN_EPS 1e-5f
#define TPC 4   // GEMM M-tiles per CTA

// ---------------- scratch ----------------
__device__ float g_P[NN * H];
__device__ float g_Q[NE * H];
__device__ float g_cat[NE * H];     // msg segment-sum only (lift half eliminated)
__device__ float g_x[NN * H];       // (1+eps1)*node_rep + lvl  (accumulated in place)
__device__ float g_R[NN * H];       // node_rep @ W3a
__device__ float g_h2[NN * H];
__device__ float g_t2[NN * H];
__device__ float g_h3[NE * H];      // h3pre: (1+eps2)*edge_rep@W3a + scatter(R)
__device__ float g_t3[NE * H];
__device__ double g_sum[5][H];
__device__ double g_sq[5][H];
__device__ float g_scale[5][H];
__device__ float g_shift[5][H];
// Preconverted weights: [n][k] bf16, 16B-granule XOR swizzle pre-applied.
__device__ __nv_bfloat16 g_Whi[6][H * H];
__device__ __nv_bfloat16 g_Wlo[6][H * H];

// ---------------- helpers ----------------
__device__ __forceinline__ uint32_t smem_u32(const void* p) {
    uint32_t a;
    asm("{ .reg .u64 t; cvta.to.shared.u64 t, %1; cvt.u32.u64 %0, t; }" : "=r"(a) : "l"(p));
    return a;
}
__device__ __forceinline__ void ldsm_x4(uint32_t r[4], uint32_t a) {
    asm volatile("ldmatrix.sync.aligned.m8n8.x4.shared.b16 {%0,%1,%2,%3}, [%4];"
                 : "=r"(r[0]), "=r"(r[1]), "=r"(r[2]), "=r"(r[3]) : "r"(a));
}
__device__ __forceinline__ void mma16816(float c[4], const uint32_t a[4], const uint32_t b[2]) {
    asm volatile("mma.sync.aligned.m16n8k16.row.col.f32.bf16.bf16.f32 "
                 "{%0,%1,%2,%3}, {%4,%5,%6,%7}, {%8,%9}, {%0,%1,%2,%3};"
                 : "+f"(c[0]), "+f"(c[1]), "+f"(c[2]), "+f"(c[3])
                 : "r"(a[0]), "r"(a[1]), "r"(a[2]), "r"(a[3]), "r"(b[0]), "r"(b[1]));
}
__device__ __forceinline__ void red4(float* p, float4 v) {
    asm volatile("red.global.add.v4.f32 [%0], {%1,%2,%3,%4};"
                 :: "l"(p), "f"(v.x), "f"(v.y), "f"(v.z), "f"(v.w) : "memory");
}
__device__ __forceinline__ float relu_aff(float x, float sc, float sh) {
    return fmaxf(fmaf(x, sc, sh), 0.f);
}

// ---------------- preconvert weights: W[k][n] -> hi/lo bf16 [n][k], pre-swizzled ----------------
__global__ void __launch_bounds__(256)
wconv_k(const float* __restrict__ W1, const float* __restrict__ W2a,
        const float* __restrict__ W2b, const float* __restrict__ W3a,
        const float* __restrict__ W3b)
{
    int m = blockIdx.x >> 3;
    int slice = blockIdx.x & 7;
    const float* src;
    switch (m) {
        case 0: src = W1; break;
        case 1: src = W1 + H * H; break;
        case 2: src = W2a; break;
        case 3: src = W2b; break;
        case 4: src = W3a; break;
        default: src = W3b; break;
    }
    int base = slice * 2048;
    for (int t = threadIdx.x; t < 2048; t += 256) {
        int idx = base + t;
        int n = idx >> 7, k = idx & 127;
        float v = src[k * H + n];
        uint32_t uv = __float_as_uint(v);
        uint32_t hb = uv & 0xFFFF0000u;
        float res = v - __uint_as_float(hb);
        uint32_t off = (uint32_t)n * 128u + ((((uint32_t)k >> 3) ^ ((uint32_t)n & 7)) << 3)
                     + ((uint32_t)k & 7);
        g_Whi[m][off] = __ushort_as_bfloat16((unsigned short)(hb >> 16));
        g_Wlo[m][off] = __float2bfloat16(res);
    }
}

// ---------------- mma.sync GEMM: C[M,128] = A[M,128] @ W, 3-way bf16 split ----------------
// AMODE 0: A = A1
// AMODE 2: A = relu(A1*scale[inSet] + shift[inSet])
// AMODE 3: A = (1+*epsp)*A1
#define SMW_HI 0
#define SMW_LO 32768
#define SMA_HI 65536
#define SMA_LO 81920
#define SM_RED 98304
#define SMEM_BYTES (98304 + 1024)

template <int AMODE, bool STATS>
__global__ void __launch_bounds__(256)
gemm_mma(const float* __restrict__ A1,
         const float* __restrict__ epsp,
         const __nv_bfloat16* __restrict__ Whi, const __nv_bfloat16* __restrict__ Wlo,
         float* __restrict__ C, int M, int inSet, int statSet)
{
    extern __shared__ char smem[];
    uint32_t sb = smem_u32(smem);
    const int tid = threadIdx.x;
    const int lane = tid & 31;
    const int wid = tid >> 5;

    // W images (32KB hi + 32KB lo), once per CTA
    {
        const uint4* shi = (const uint4*)Whi;
        const uint4* slo = (const uint4*)Wlo;
        uint4* dhi = (uint4*)(smem + SMW_HI);
        uint4* dlo = (uint4*)(smem + SMW_LO);
#pragma unroll
        for (int i = 0; i < 8; i++) {
            dhi[tid + i * 256] = shi[tid + i * 256];
            dlo[tid + i * 256] = slo[tid + i * 256];
        }
    }
    if (STATS) ((float*)(smem + SM_RED))[tid] = 0.f;  // sum[128] | sq[128]

    float alpha = 1.0f;
    if (AMODE == 3) alpha = 1.0f + __ldg(epsp);

    const int wm = wid & 1;        // row group (32 rows)
    const int wn = wid >> 1;       // col group (32 cols)
    const int rb = wm * 32;
    const int cbc = wn * 32;
    const int gq = lane >> 2, rq = lane & 3;

    for (int t = 0; t < TPC; t++) {
        const int row0 = (blockIdx.x * TPC + t) * 64;
        if (row0 >= M) break;
        __syncthreads();   // previous tile's readers done before overwriting A

        // load A rows (64 x 128), transform, split hi/lo, store swizzled
        {
            const int r = tid >> 2;
            const int cq = tid & 3;
            const int arow = row0 + r;
            const bool valid = arow < M;
            const float* a1p = A1 + (size_t)arow * H + cq * 32;
#pragma unroll
            for (int g = 0; g < 4; g++) {
                float f[8];
                if (valid) {
                    float4 u0 = *(const float4*)(a1p + g * 8);
                    float4 u1 = *(const float4*)(a1p + g * 8 + 4);
                    f[0] = u0.x; f[1] = u0.y; f[2] = u0.z; f[3] = u0.w;
                    f[4] = u1.x; f[5] = u1.y; f[6] = u1.z; f[7] = u1.w;
                    if (AMODE == 3) {
#pragma unroll
                        for (int j = 0; j < 8; j++) f[j] *= alpha;
                    } else if (AMODE == 2) {
                        int c0 = cq * 32 + g * 8;
#pragma unroll
                        for (int j = 0; j < 8; j++)
                            f[j] = relu_aff(f[j], g_scale[inSet][c0 + j], g_shift[inSet][c0 + j]);
                    }
                } else {
#pragma unroll
                    for (int j = 0; j < 8; j++) f[j] = 0.f;
                }
                uint32_t hv[4], lv[4];
#pragma unroll
                for (int j = 0; j < 4; j++) {
                    float a = f[2 * j], b = f[2 * j + 1];
                    uint32_t ua = __float_as_uint(a), ub = __float_as_uint(b);
                    hv[j] = __byte_perm(ua, ub, 0x7632);
                    float ra = a - __uint_as_float(ua & 0xFFFF0000u);
                    float rb2 = b - __uint_as_float(ub & 0xFFFF0000u);
                    __nv_bfloat162 lo2 = __floats2bfloat162_rn(ra, rb2);
                    lv[j] = *(uint32_t*)&lo2;
                }
                uint32_t gran = (uint32_t)((cq * 4 + g) ^ (r & 7));
                uint32_t off = (uint32_t)r * 256u + gran * 16u;
                *(uint4*)(smem + SMA_HI + off) = make_uint4(hv[0], hv[1], hv[2], hv[3]);
                *(uint4*)(smem + SMA_LO + off) = make_uint4(lv[0], lv[1], lv[2], lv[3]);
            }
        }
        __syncthreads();

        float acc[2][4][4];
#pragma unroll
        for (int mt = 0; mt < 2; mt++)
#pragma unroll
            for (int j = 0; j < 4; j++)
#pragma unroll
                for (int q = 0; q < 4; q++) acc[mt][j][q] = 0.f;

#pragma unroll
        for (int ks = 0; ks < 8; ks++) {
            const uint32_t kg = (uint32_t)ks * 2u;
            uint32_t ahi[2][4], alo[2][4];
#pragma unroll
            for (int mt = 0; mt < 2; mt++) {
                uint32_t rowA = (uint32_t)(rb + mt * 16 + (lane & 15));
                uint32_t gran = (kg + (uint32_t)(lane >> 4)) ^ (rowA & 7u);
                uint32_t a = sb + SMA_HI + rowA * 256u + gran * 16u;
                ldsm_x4(ahi[mt], a);
                ldsm_x4(alo[mt], a + 16384u);
            }
#pragma unroll
            for (int pr = 0; pr < 2; pr++) {
                uint32_t rowB = (uint32_t)(cbc + pr * 16 + ((lane >> 4) << 3) + (lane & 7));
                uint32_t kgr = kg + (uint32_t)((lane >> 3) & 1);
                uint32_t b = sb + SMW_HI + rowB * 256u + ((kgr ^ (rowB & 7u)) * 16u);
                uint32_t bh[4], bl[4];
                ldsm_x4(bh, b);
                ldsm_x4(bl, b + 32768u);
#pragma unroll
                for (int mt = 0; mt < 2; mt++) {
                    mma16816(acc[mt][pr * 2],     ahi[mt], bh);
                    mma16816(acc[mt][pr * 2],     ahi[mt], bl);
                    mma16816(acc[mt][pr * 2],     alo[mt], bh);
                    mma16816(acc[mt][pr * 2 + 1], ahi[mt], bh + 2);
                    mma16816(acc[mt][pr * 2 + 1], ahi[mt], bl + 2);
                    mma16816(acc[mt][pr * 2 + 1], alo[mt], bh + 2);
                }
            }
        }

        // epilogue: global stores
#pragma unroll
        for (int mt = 0; mt < 2; mt++) {
            int r0 = row0 + rb + mt * 16 + gq;
#pragma unroll
            for (int j = 0; j < 4; j++) {
                int col = cbc + j * 8 + rq * 2;
                if (r0 < M)
                    *(float2*)(C + (size_t)r0 * H + col) = make_float2(acc[mt][j][0], acc[mt][j][1]);
                if (r0 + 8 < M)
                    *(float2*)(C + (size_t)(r0 + 8) * H + col) = make_float2(acc[mt][j][2], acc[mt][j][3]);
            }
        }

        if (STATS) {
            float* s_sum = (float*)(smem + SM_RED);
            float* s_sq  = s_sum + 128;
#pragma unroll
            for (int j = 0; j < 4; j++) {
                float se = 0.f, so = 0.f, qe = 0.f, qo = 0.f;
#pragma unroll
                for (int mt = 0; mt < 2; mt++) {
                    float c0 = acc[mt][j][0], c1 = acc[mt][j][1];
                    float c2 = acc[mt][j][2], c3 = acc[mt][j][3];
                    se += c0 + c2; so += c1 + c3;
                    qe = fmaf(c0, c0, qe); qe = fmaf(c2, c2, qe);
                    qo = fmaf(c1, c1, qo); qo = fmaf(c3, c3, qo);
                }
#pragma unroll
                for (int o = 16; o >= 4; o >>= 1) {
                    se += __shfl_down_sync(0xFFFFFFFFu, se, o);
                    so += __shfl_down_sync(0xFFFFFFFFu, so, o);
                    qe += __shfl_down_sync(0xFFFFFFFFu, qe, o);
                    qo += __shfl_down_sync(0xFFFFFFFFu, qo, o);
                }
                if (lane < 4) {
                    int col = cbc + j * 8 + lane * 2;
                    atomicAdd(&s_sum[col],     se);
                    atomicAdd(&s_sum[col + 1], so);
                    atomicAdd(&s_sq[col],      qe);
                    atomicAdd(&s_sq[col + 1],  qo);
                }
            }
        }
    }

    if (STATS) {
        __syncthreads();
        float* s_sum = (float*)(smem + SM_RED);
        if (tid < 128)      atomicAdd(&g_sum[statSet][tid],       (double)s_sum[tid]);
        else                atomicAdd(&g_sq[statSet][tid - 128],  (double)s_sum[tid]);
    }
}

// ---------------- stats over msg_raw[i] = P[n_i] + Q[e_i] ----------------
__global__ void __launch_bounds__(256)
stats_msg_k(const int* __restrict__ node_idx, const int* __restrict__ edge_idx)
{
    const int lane = threadIdx.x & 31;
    const int w = threadIdx.x >> 5;
    const int c4 = lane << 2;
    float4 s = make_float4(0.f, 0.f, 0.f, 0.f);
    float4 q = make_float4(0.f, 0.f, 0.f, 0.f);
    for (int i = blockIdx.x * 8 + w; i < NI; i += gridDim.x * 8) {
        int n = node_idx[i], e = edge_idx[i];
        float4 p  = *(const float4*)(g_P + (size_t)n * H + c4);
        float4 qq = *(const float4*)(g_Q + (size_t)e * H + c4);
        float vx = p.x + qq.x, vy = p.y + qq.y, vz = p.z + qq.z, vw = p.w + qq.w;
        s.x += vx; s.y += vy; s.z += vz; s.w += vw;
        q.x = fmaf(vx, vx, q.x); q.y = fmaf(vy, vy, q.y);
        q.z = fmaf(vz, vz, q.z); q.w = fmaf(vw, vw, q.w);
    }
    __shared__ float red[8][128];
    red[w][c4 + 0] = s.x; red[w][c4 + 1] = s.y; red[w][c4 + 2] = s.z; red[w][c4 + 3] = s.w;
    __syncthreads();
    if (threadIdx.x < 128) {
        float t = 0.f;
#pragma unroll
        for (int r = 0; r < 8; r++) t += red[r][threadIdx.x];
        atomicAdd(&g_sum[0][threadIdx.x], (double)t);
    }
    __syncthreads();
    red[w][c4 + 0] = q.x; red[w][c4 + 1] = q.y; red[w][c4 + 2] = q.z; red[w][c4 + 3] = q.w;
    __syncthreads();
    if (threadIdx.x < 128) {
        float t = 0.f;
#pragma unroll
        for (int r = 0; r < 8; r++) t += red[r][threadIdx.x];
        atomicAdd(&g_sq[0][threadIdx.x], (double)t);
    }
}

// ---------------- column stats of a dense [M,128] matrix ----------------
__global__ void __launch_bounds__(256)
colstats_k(const float* __restrict__ X, int M, int set)
{
    const int lane = threadIdx.x & 31;
    const int w = threadIdx.x >> 5;
    const int c4 = lane << 2;
    float4 s = make_float4(0.f, 0.f, 0.f, 0.f);
    float4 q = make_float4(0.f, 0.f, 0.f, 0.f);
    for (int r = blockIdx.x * 8 + w; r < M; r += gridDim.x * 8) {
        float4 v = *(const float4*)(X + (size_t)r * H + c4);
        s.x += v.x; s.y += v.y; s.z += v.z; s.w += v.w;
        q.x = fmaf(v.x, v.x, q.x); q.y = fmaf(v.y, v.y, q.y);
        q.z = fmaf(v.z, v.z, q.z); q.w = fmaf(v.w, v.w, q.w);
    }
    __shared__ float red[8][128];
    red[w][c4 + 0] = s.x; red[w][c4 + 1] = s.y; red[w][c4 + 2] = s.z; red[w][c4 + 3] = s.w;
    __syncthreads();
    if (threadIdx.x < 128) {
        float t = 0.f;
#pragma unroll
        for (int r = 0; r < 8; r++) t += red[r][threadIdx.x];
        atomicAdd(&g_sum[set][threadIdx.x], (double)t);
    }
    __syncthreads();
    red[w][c4 + 0] = q.x; red[w][c4 + 1] = q.y; red[w][c4 + 2] = q.z; red[w][c4 + 3] = q.w;
    __syncthreads();
    if (threadIdx.x < 128) {
        float t = 0.f;
#pragma unroll
        for (int r = 0; r < 8; r++) t += red[r][threadIdx.x];
        atomicAdd(&g_sq[set][threadIdx.x], (double)t);
    }
}

// ---------------- finalize BN stats ----------------
__global__ void finalize_k(int set, const float* __restrict__ g,
                           const float* __restrict__ b, float invN)
{
    int j = threadIdx.x;
    double mean = g_sum[set][j] * (double)invN;
    double var = g_sq[set][j] * (double)invN - mean * mean;
    float sc = g[j] * rsqrtf((float)var + BN_EPS);
    g_scale[set][j] = sc;
    g_shift[set][j] = fmaf(-(float)mean, sc, b[j]);
}

// ---------------- x init: x = (1+eps1)*node_rep ----------------
__global__ void __launch_bounds__(256)
scalex_k(const float* __restrict__ node_rep, const float* __restrict__ epsp)
{
    int t = blockIdx.x * blockDim.x + threadIdx.x;
    if (t >= NN * H / 4) return;
    float alpha = 1.0f + __ldg(epsp);
    float4 v = ((const float4*)node_rep)[t];
    ((float4*)g_x)[t] = make_float4(alpha * v.x, alpha * v.y, alpha * v.z, alpha * v.w);
}

// ---------------- catm pass: cat[e] += msg, x[n] -= msg ----------------
__global__ void __launch_bounds__(256)
catm_k(const int* __restrict__ node_idx, const int* __restrict__ edge_idx)
{
    const int lane = threadIdx.x & 31;
    const int w = threadIdx.x >> 5;
    const int c4 = lane << 2;
    int i = blockIdx.x * 8 + w;
    if (i >= NI) return;
    int n = node_idx[i], e = edge_idx[i];
    float4 p = *(const float4*)(g_P + (size_t)n * H + c4);
    float4 q = *(const float4*)(g_Q + (size_t)e * H + c4);
    float4 sc = *(const float4*)&g_scale[0][c4];
    float4 sh = *(const float4*)&g_shift[0][c4];
    float4 m;
    m.x = relu_aff(p.x + q.x, sc.x, sh.x);
    m.y = relu_aff(p.y + q.y, sc.y, sh.y);
    m.z = relu_aff(p.z + q.z, sc.z, sh.z);
    m.w = relu_aff(p.w + q.w, sc.w, sh.w);
    red4(g_cat + (size_t)e * H + c4, m);
    red4(g_x + (size_t)n * H + c4, make_float4(-m.x, -m.y, -m.z, -m.w));
}

// ---------------- lvl pass 2: x[n] += cat[e_i] ----------------
__global__ void __launch_bounds__(256)
lvl2_k(const int* __restrict__ node_idx, const int* __restrict__ edge_idx)
{
    const int lane = threadIdx.x & 31;
    const int w = threadIdx.x >> 5;
    const int c4 = lane << 2;
    int i = blockIdx.x * 8 + w;
    if (i >= NI) return;
    int n = node_idx[i], e = edge_idx[i];
    float4 cv = *(const float4*)(g_cat + (size_t)e * H + c4);
    red4(g_x + (size_t)n * H + c4, cv);
}

// ---------------- R scatter: h3pre[e] += R[n_i] ----------------
__global__ void __launch_bounds__(256)
rscat_k(const int* __restrict__ node_idx, const int* __restrict__ edge_idx)
{
    const int lane = threadIdx.x & 31;
    const int w = threadIdx.x >> 5;
    const int c4 = lane << 2;
    int i = blockIdx.x * 8 + w;
    if (i >= NI) return;
    int n = node_idx[i], e = edge_idx[i];
    float4 r = *(const float4*)(g_R + (size_t)n * H + c4);
    red4(g_h3 + (size_t)e * H + c4, r);
}

// ---------------- final elementwise bn_relu ----------------
__global__ void __launch_bounds__(256)
bnout_k(const float* __restrict__ in, int set, float* __restrict__ out, int n4)
{
    int t = blockIdx.x * blockDim.x + threadIdx.x;
    if (t >= n4) return;
    int c4 = (t & 31) << 2;
    float4 v = ((const float4*)in)[t];
    float4 sc = *(const float4*)&g_scale[set][c4];
    float4 sh = *(const float4*)&g_shift[set][c4];
    float4 o;
    o.x = relu_aff(v.x, sc.x, sh.x);
    o.y = relu_aff(v.y, sc.y, sh.y);
    o.z = relu_aff(v.z, sc.z, sh.z);
    o.w = relu_aff(v.w, sc.w, sh.w);
    ((float4*)out)[t] = o;
}

// ---------------- launch: forked-stream graph ----------------
extern "C" void kernel_launch(void* const* d_in, const int* in_sizes, int n_in,
                              void* d_out, int out_size)
{
    const float* node_rep = (const float*)d_in[0];
    const float* edge_rep = (const float*)d_in[1];
    const int*   node_idx = (const int*)d_in[2];
    const int*   edge_idx = (const int*)d_in[3];
    const float* W1  = (const float*)d_in[4];
    const float* g1  = (const float*)d_in[5];
    const float* b1  = (const float*)d_in[6];
    const float* W2a = (const float*)d_in[7];
    const float* g2a = (const float*)d_in[8];
    const float* b2a = (const float*)d_in[9];
    const float* W2b = (const float*)d_in[10];
    const float* g2b = (const float*)d_in[11];
    const float* b2b = (const float*)d_in[12];
    const float* W3a = (const float*)d_in[13];
    const float* g3a = (const float*)d_in[14];
    const float* b3a = (const float*)d_in[15];
    const float* W3b = (const float*)d_in[16];
    const float* g3b = (const float*)d_in[17];
    const float* b3b = (const float*)d_in[18];
    const float* eps1 = (const float*)d_in[19];
    const float* eps2 = (const float*)d_in[20];

    float *P, *Q, *cat, *x, *R, *h2, *t2, *h3, *t3;
    double *sumP, *sqP;
    __nv_bfloat16 *Whi, *Wlo;
    cudaGetSymbolAddress((void**)&P,    g_P);
    cudaGetSymbolAddress((void**)&Q,    g_Q);
    cudaGetSymbolAddress((void**)&cat,  g_cat);
    cudaGetSymbolAddress((void**)&x,    g_x);
    cudaGetSymbolAddress((void**)&R,    g_R);
    cudaGetSymbolAddress((void**)&h2,   g_h2);
    cudaGetSymbolAddress((void**)&t2,   g_t2);
    cudaGetSymbolAddress((void**)&h3,   g_h3);
    cudaGetSymbolAddress((void**)&t3,   g_t3);
    cudaGetSymbolAddress((void**)&sumP, g_sum);
    cudaGetSymbolAddress((void**)&sqP,  g_sq);
    cudaGetSymbolAddress((void**)&Whi,  g_Whi);
    cudaGetSymbolAddress((void**)&Wlo,  g_Wlo);

    cudaFuncSetAttribute(gemm_mma<0, false>, cudaFuncAttributeMaxDynamicSharedMemorySize, SMEM_BYTES);
    cudaFuncSetAttribute(gemm_mma<0, true>,  cudaFuncAttributeMaxDynamicSharedMemorySize, SMEM_BYTES);
    cudaFuncSetAttribute(gemm_mma<2, true>,  cudaFuncAttributeMaxDynamicSharedMemorySize, SMEM_BYTES);
    cudaFuncSetAttribute(gemm_mma<3, false>, cudaFuncAttributeMaxDynamicSharedMemorySize, SMEM_BYTES);

    float* node_out = (float*)d_out;
    float* edge_out = (float*)d_out + (size_t)NN * H;

    const int TN = (NN + 63) / 64;
    const int TE = (NE + 63) / 64;
    const int GN = (TN + TPC - 1) / TPC;
    const int GE = (TE + TPC - 1) / TPC;

    cudaStream_t sA, sB;
    cudaStreamCreateWithFlags(&sA, cudaStreamNonBlocking);
    cudaStreamCreateWithFlags(&sB, cudaStreamNonBlocking);
    cudaEvent_t eFork, eW, eP, eZero, eEdge;
    cudaEventCreateWithFlags(&eFork, cudaEventDisableTiming);
    cudaEventCreateWithFlags(&eW,    cudaEventDisableTiming);
    cudaEventCreateWithFlags(&eP,    cudaEventDisableTiming);
    cudaEventCreateWithFlags(&eZero, cudaEventDisableTiming);
    cudaEventCreateWithFlags(&eEdge, cudaEventDisableTiming);

    // fork sA, sB off the capture-origin (default) stream
    cudaEventRecord(eFork, 0);
    cudaStreamWaitEvent(sA, eFork, 0);
    cudaStreamWaitEvent(sB, eFork, 0);

    // sB: zero cat + stat accumulators, then the ENTIRE edge branch:
    //   E3 = (1+eps2)*edge_rep@W3a -> h3 ; R = node_rep@W3a ; h3 += scatter(R)
    //   colstats(h3) -> BN3a ; gemm3b ; bnout.   (independent of P/Q/BN1!)
    cudaMemsetAsync(cat,  0, (size_t)NE * H * sizeof(float), sB);
    cudaMemsetAsync(sumP, 0, 5 * H * sizeof(double), sB);
    cudaMemsetAsync(sqP,  0, 5 * H * sizeof(double), sB);
    cudaEventRecord(eZero, sB);

    // s0: weight conversion
    wconv_k<<<48, 256>>>(W1, W2a, W2b, W3a, W3b);
    cudaEventRecord(eW, 0);

    // sB edge branch
    cudaStreamWaitEvent(sB, eW, 0);
    gemm_mma<3, false><<<GE, 256, SMEM_BYTES, sB>>>(edge_rep, eps2,
                                                    Whi + 4 * H * H, Wlo + 4 * H * H, h3, NE, 0, 0);
    gemm_mma<0, false><<<GN, 256, SMEM_BYTES, sB>>>(node_rep, nullptr,
                                                    Whi + 4 * H * H, Wlo + 4 * H * H, R, NN, 0, 0);
    rscat_k<<<NI / 8, 256, 0, sB>>>(node_idx, edge_idx);
    colstats_k<<<1184, 256, 0, sB>>>(h3, NE, 3);
    finalize_k<<<1, 128, 0, sB>>>(3, g3a, b3a, 1.0f / NE);
    gemm_mma<2, true><<<GE, 256, SMEM_BYTES, sB>>>(h3, nullptr,
                                                   Whi + 5 * H * H, Wlo + 5 * H * H, t3, NE, 3, 4);
    finalize_k<<<1, 128, 0, sB>>>(4, g3b, b3b, 1.0f / NE);
    bnout_k<<<(NE * H / 4 + 255) / 256, 256, 0, sB>>>(t3, 4, edge_out, NE * H / 4);
    cudaEventRecord(eEdge, sB);

    // sA: P = node_rep @ W1[:128]
    cudaStreamWaitEvent(sA, eW, 0);
    gemm_mma<0, false><<<GN, 256, SMEM_BYTES, sA>>>(node_rep, nullptr,
                                                    Whi + 0 * H * H, Wlo + 0 * H * H, P, NN, 0, 0);
    cudaEventRecord(eP, sA);

    // s0: Q = edge_rep @ W1[128:], x init, BN1 stats, msg scatter, node path
    gemm_mma<0, false><<<GE, 256, SMEM_BYTES>>>(edge_rep, nullptr,
                                                Whi + 1 * H * H, Wlo + 1 * H * H, Q, NE, 0, 0);
    scalex_k<<<(NN * H / 4 + 255) / 256, 256>>>(node_rep, eps1);
    cudaStreamWaitEvent(0, eP, 0);
    cudaStreamWaitEvent(0, eZero, 0);
    stats_msg_k<<<1184, 256>>>(node_idx, edge_idx);
    finalize_k<<<1, 128>>>(0, g1, b1, 1.0f / NI);
    catm_k<<<NI / 8, 256>>>(node_idx, edge_idx);
    lvl2_k<<<NI / 8, 256>>>(node_idx, edge_idx);
    gemm_mma<0, true><<<GN, 256, SMEM_BYTES>>>(x, nullptr,
                                               Whi + 2 * H * H, Wlo + 2 * H * H, h2, NN, 0, 1);
    finalize_k<<<1, 128>>>(1, g2a, b2a, 1.0f / NN);
    gemm_mma<2, true><<<GN, 256, SMEM_BYTES>>>(h2, nullptr,
                                               Whi + 3 * H * H, Wlo + 3 * H * H, t2, NN, 1, 2);
    finalize_k<<<1, 128>>>(2, g2b, b2b, 1.0f / NN);
    bnout_k<<<(NN * H / 4 + 255) / 256, 256>>>(t2, 2, node_out, NN * H / 4);

    // join edge branch back into origin stream
    cudaStreamWaitEvent(0, eEdge, 0);

    cudaEventDestroy(eFork);
    cudaEventDestroy(eW);
    cudaEventDestroy(eP);
    cudaEventDestroy(eZero);
    cudaEventDestroy(eEdge);
    cudaStreamDestroy(sA);
    cudaStreamDestroy(sB);
}